// round 9
// baseline (speedup 1.0000x reference)
#include <cuda_runtime.h>
#include <cuda_bf16.h>
#include <math.h>
#include <stdint.h>

// Problem constants
#define Bb 128
#define Tt 32
#define Ee 512
#define Hh 512
#define Ll 256
#define Vv 16000

#define NCH_G  60      // gates: K2=3840 (folded)
#define NCH_PQ 48      // pq: K2=3072 (folded)
#define QROWS  192
#define QCH    12      // qx chunks of 64 over K=768 (unfolded hi/lo)
#define REC_CTAS 48
#define QX_CTAS  84
#define TOT_CTAS 132

// Output layout: p_mus, p_sigmas, q_mus, q_sigmas, q_xs
#define OFF_PMU  ((size_t)0)
#define OFF_PSIG ((size_t)Tt * Bb * Ll)
#define OFF_QMU  ((size_t)2 * Tt * Bb * Ll)
#define OFF_QSIG ((size_t)3 * Tt * Bb * Ll)
#define OFF_QX   ((size_t)4 * Tt * Bb * Ll)

// ---------------- device scratch ----------------
__device__ float g_emb[Tt * Bb * Ee];
__device__ float g_bsum[4 * Hh];
__device__ float g_bias_pq[1024];
__device__ float g_c[Bb * Hh];
__device__ float g_pqp[6][Bb * 1024];
__device__ float g_gp[3][Bb * 2048];
__device__ int g_flagZ[Tt];
__device__ int g_flagQ[Tt];
__device__ int g_bar[Tt + 2][4];

// Weight images (once)
__device__ __align__(16) __nv_bfloat16 gBg[(size_t)16 * NCH_G * 8192];
__device__ __align__(16) __nv_bfloat16 gBpq[(size_t)8 * NCH_PQ * 8192];
__device__ __align__(16) __nv_bfloat16 gBqx[(size_t)QX_CTAS * QCH * 2 * QROWS * 64];
// A images: pq/gates folded single; qx triple-buffered
__device__ __align__(16) __nv_bfloat16 gAg[NCH_G * 8192];
__device__ __align__(16) __nv_bfloat16 gApq[NCH_PQ * 8192];
__device__ __align__(16) __nv_bfloat16 gAqx3[3][QCH * 16384];

__device__ __forceinline__ float sigf(float x) { return 1.0f / (1.0f + expf(-x)); }

__device__ __forceinline__ uint32_t s2u(const void* p) {
    uint32_t a;
    asm("{ .reg .u64 t; cvta.to.shared.u64 t, %1; cvt.u32.u64 %0, t; }" : "=r"(a) : "l"(p));
    return a;
}
__device__ __forceinline__ void cpasync16(uint32_t dst, const void* src) {
    asm volatile("cp.async.cg.shared.global [%0], [%1], 16;"
                 :: "r"(dst), "l"(__cvta_generic_to_global(src)) : "memory");
}
__device__ __forceinline__ void ldmatrix_x4(uint32_t* r, uint32_t addr) {
    asm volatile("ldmatrix.sync.aligned.m8n8.x4.shared.b16 {%0,%1,%2,%3}, [%4];"
                 : "=r"(r[0]), "=r"(r[1]), "=r"(r[2]), "=r"(r[3]) : "r"(addr));
}
__device__ __forceinline__ void mma16816(float* c, const uint32_t* a, uint32_t b0, uint32_t b1) {
    asm volatile(
        "mma.sync.aligned.m16n8k16.row.col.f32.bf16.bf16.f32 "
        "{%0,%1,%2,%3}, {%4,%5,%6,%7}, {%8,%9}, {%0,%1,%2,%3};"
        : "+f"(c[0]), "+f"(c[1]), "+f"(c[2]), "+f"(c[3])
        : "r"(a[0]), "r"(a[1]), "r"(a[2]), "r"(a[3]), "r"(b0), "r"(b1));
}
__device__ __forceinline__ size_t ipos(int k2, int m) {
    return (((size_t)(k2 >> 6) * 128 + m) << 6) + (k2 & 63);
}
__device__ __forceinline__ size_t qpos(int k, int m, int sel) {
    return (size_t)(k >> 6) * 16384 + sel * 8192 + m * 64 + (k & 63);
}
__device__ __forceinline__ unsigned long long pk4(__nv_bfloat16 a, __nv_bfloat16 b,
                                                  __nv_bfloat16 c, __nv_bfloat16 d) {
    union { __nv_bfloat16 h[4]; unsigned long long u; } t;
    t.h[0] = a; t.h[1] = b; t.h[2] = c; t.h[3] = d;
    return t.u;
}
__device__ __forceinline__ void cvt4(float4 v, unsigned long long& hi, unsigned long long& lo) {
    __nv_bfloat16 h0 = __float2bfloat16(v.x), h1 = __float2bfloat16(v.y);
    __nv_bfloat16 h2 = __float2bfloat16(v.z), h3 = __float2bfloat16(v.w);
    hi = pk4(h0, h1, h2, h3);
    lo = pk4(__float2bfloat16(v.x - __bfloat162float(h0)),
             __float2bfloat16(v.y - __bfloat162float(h1)),
             __float2bfloat16(v.z - __bfloat162float(h2)),
             __float2bfloat16(v.w - __bfloat162float(h3)));
}
__device__ __forceinline__ void st8(__nv_bfloat16* p, unsigned long long v) {
    *(unsigned long long*)p = v;
}

// barrier across the 48 recurrence CTAs (per-(step,phase) counter, prep-zeroed)
__device__ __forceinline__ void bar48(int* ctr) {
    __threadfence();
    __syncthreads();
    if (threadIdx.x == 0) {
        atomicAdd(ctr, 1);
        volatile int* v = ctr;
        while (*v < REC_CTAS) { }
    }
    __syncthreads();
}
__device__ __forceinline__ void waitflag(int* f, int target) {
    if (threadIdx.x == 0) {
        volatile int* v = f;
        while (*v < target) { }
    }
    __syncthreads();
}
__device__ __forceinline__ void setflag(int* f) {
    __threadfence();
    __syncthreads();
    if (threadIdx.x == 0) atomicAdd(f, 1);
}

// ---------------- one-time prep ----------------
#define N_EMB4 (Tt * Bb * Ee / 4)
#define GAG_Z  (NCH_G * 8192 * 2 / 16)
#define N_FLAGS (Tt + Tt + (Tt + 2) * 4)
__global__ void prep_misc_kernel(const float* __restrict__ b_ih, const float* __restrict__ b_hh,
                                 const float* __restrict__ qz_b, const float* __restrict__ prior_b,
                                 const float* __restrict__ embed_W, const int* __restrict__ captions) {
    int i4 = blockIdx.x * blockDim.x + threadIdx.x;
    if (i4 < N_EMB4) {
        int j = i4 * 4;
        int tb = j >> 9, e = j & 511;
        int t = tb / Bb, b = tb % Bb;
        *(float4*)(g_emb + j) = *(const float4*)(embed_W + (size_t)captions[b * Tt + t] * Ee + e);
        return;
    }
    i4 -= N_EMB4;
    if (i4 < 512) {
        int n = i4 * 4;
        float4 a = *(const float4*)(b_ih + n), b = *(const float4*)(b_hh + n);
        *(float4*)(g_bsum + n) = make_float4(a.x + b.x, a.y + b.y, a.z + b.z, a.w + b.w);
        return;
    }
    i4 -= 512;
    if (i4 < 256) {
        int n = i4 * 4;
        *(float4*)(g_bias_pq + n) = (n < 512) ? *(const float4*)(qz_b + n)
                                              : *(const float4*)(prior_b + n - 512);
        return;
    }
    i4 -= 256;
    if (i4 < Bb * Hh / 4) { *(float4*)(g_c + i4 * 4) = make_float4(0, 0, 0, 0); return; }
    i4 -= Bb * Hh / 4;
    if (i4 < GAG_Z) { *(float4*)((char*)gAg + (size_t)i4 * 16) = make_float4(0, 0, 0, 0); return; }
    i4 -= GAG_Z;
    if (i4 < N_FLAGS) {
        if (i4 < Tt) g_flagZ[i4] = 0;
        else if (i4 < 2 * Tt) g_flagQ[i4 - Tt] = 0;
        else { int j = i4 - 2 * Tt; g_bar[j >> 2][j & 3] = 0; }
    }
}
#define PREP_MISC_TOT (N_EMB4 + 512 + 256 + Bb * Hh / 4 + GAG_Z + N_FLAGS)

// gates weights: N=2048, K order [e(512), z(256), h(512)], fold [hi|lo|hi]
__global__ void prep_wg_kernel(const float* __restrict__ W_ih, const float* __restrict__ W_hh) {
    int idx = blockIdx.x * blockDim.x + threadIdx.x;
    if (idx >= 2048 * 320) return;
    int n = idx / 320, k = (idx - n * 320) * 4;
    float4 v = (k < 768) ? *(const float4*)(W_ih + (size_t)n * 768 + k)
                         : *(const float4*)(W_hh + (size_t)n * 512 + (k - 768));
    unsigned long long hi, lo;
    cvt4(v, hi, lo);
    int tile = n >> 7, row = n & 127;
    __nv_bfloat16* base = gBg + (size_t)tile * NCH_G * 8192;
    st8(base + ipos(k, row), hi);
    st8(base + ipos(k + 1280, row), lo);
    st8(base + ipos(k + 2560, row), hi);
}

// pq weights: N=1024 (qz 0-511, prior 512-1023 padded over e), K order [e, h]
__global__ void prep_wpq_kernel(const float* __restrict__ qz_W, const float* __restrict__ prior_W) {
    int idx = blockIdx.x * blockDim.x + threadIdx.x;
    if (idx >= 1024 * 256) return;
    int n = idx >> 8, k = (idx & 255) << 2;
    float4 v;
    if (n < 512) v = *(const float4*)(qz_W + (size_t)n * 1024 + k);
    else if (k < 512) v = make_float4(0, 0, 0, 0);
    else v = *(const float4*)(prior_W + (size_t)(n - 512) * 512 + (k - 512));
    unsigned long long hi, lo;
    cvt4(v, hi, lo);
    int tile = n >> 7, row = n & 127;
    __nv_bfloat16* base = gBpq + (size_t)tile * NCH_PQ * 8192;
    st8(base + ipos(k, row), hi);
    st8(base + ipos(k + 1024, row), lo);
    st8(base + ipos(k + 2048, row), hi);
}

// qx weights unfolded: per tile/chunk: [hi 192x64 | lo 192x64]
__global__ void prep_wqx_kernel(const float* __restrict__ qx_W) {
    int idx = blockIdx.x * blockDim.x + threadIdx.x;
    if (idx >= 16128 * 192) return;
    int n = idx / 192, k = (idx - n * 192) * 4;
    float4 v = (n < Vv) ? *(const float4*)(qx_W + (size_t)n * 768 + k)
                        : make_float4(0, 0, 0, 0);
    unsigned long long hi, lo;
    cvt4(v, hi, lo);
    int tile = n / QROWS, row = n - tile * QROWS;
    __nv_bfloat16* base = gBqx + (size_t)tile * (QCH * 2 * QROWS * 64);
    size_t off = (size_t)(k >> 6) * (2 * QROWS * 64) + row * 64 + (k & 63);
    st8(base + off, hi);
    st8(base + off + QROWS * 64, lo);
}

// ---------------- folded GEMM body (pq/gates; 128x128 tiles) ----------------
#define PITCH 144
#define STAGE_B 18432
#define SSZ128 ((128 + 128) * PITCH)

__device__ __forceinline__ void load_stage(uint32_t st, const char* srcA, const char* srcB, int tid) {
#pragma unroll
    for (int j = 0; j < 4; j++) {
        int i = tid + j * 256;
        cpasync16(st + (i >> 3) * PITCH + (i & 7) * 16, srcA + i * 16);
    }
#pragma unroll
    for (int j = 0; j < 4; j++) {
        int i = tid + j * 256;
        cpasync16(st + STAGE_B + (i >> 3) * PITCH + (i & 7) * 16, srcB + i * 16);
    }
    asm volatile("cp.async.commit_group;" ::: "memory");
}

__device__ __forceinline__ void gemm_body(
    const __nv_bfloat16* __restrict__ Aimg, const __nv_bfloat16* __restrict__ Bimg,
    int nchunk, float* __restrict__ dst, int ldc, int n0, char* smem) {
    const uint32_t sb = s2u(smem);
    const int tid = threadIdx.x;
    const int wid = tid >> 5;
    const int lane = tid & 31;
    const int warp_m = wid >> 2;
    const int warp_n = wid & 3;

    const char* gA = (const char*)Aimg;
    const char* gB = (const char*)Bimg;

    float acc[4][4][4];
#pragma unroll
    for (int i = 0; i < 4; i++)
#pragma unroll
        for (int j = 0; j < 4; j++)
#pragma unroll
            for (int q = 0; q < 4; q++) acc[i][j][q] = 0.0f;

    const int a_row = lane & 15;
    const int a_coff = (lane >> 4) << 4;
    const int b_row = ((lane >> 4) << 3) | (lane & 7);
    const int b_coff = ((lane >> 3) & 1) << 4;

#pragma unroll
    for (int s = 0; s < 3; s++)
        load_stage(sb + s * SSZ128, gA + (size_t)s * 16384, gB + (size_t)s * 16384, tid);

    int slot = 0;
    for (int c = 0; c < nchunk; c++) {
        asm volatile("cp.async.wait_group 2;" ::: "memory");
        __syncthreads();

        const uint32_t As = sb + slot * SSZ128;
        const uint32_t Bs = As + STAGE_B;
#pragma unroll
        for (int ks = 0; ks < 4; ks++) {
            uint32_t a[4][4];
#pragma unroll
            for (int mi = 0; mi < 4; mi++)
                ldmatrix_x4(a[mi], As + (uint32_t)(warp_m * 64 + mi * 16 + a_row) * PITCH +
                                    ks * 32 + a_coff);
#pragma unroll
            for (int jp = 0; jp < 2; jp++) {
                uint32_t b[4];
                ldmatrix_x4(b, Bs + (uint32_t)(warp_n * 32 + jp * 16 + b_row) * PITCH +
                                ks * 32 + b_coff);
#pragma unroll
                for (int mi = 0; mi < 4; mi++) {
                    mma16816(acc[mi][jp * 2 + 0], a[mi], b[0], b[1]);
                    mma16816(acc[mi][jp * 2 + 1], a[mi], b[2], b[3]);
                }
            }
        }
        __syncthreads();
        if (c + 3 < nchunk)
            load_stage(sb + slot * SSZ128, gA + (size_t)(c + 3) * 16384,
                       gB + (size_t)(c + 3) * 16384, tid);
        else
            asm volatile("cp.async.commit_group;" ::: "memory");
        slot = (slot == 2) ? 0 : slot + 1;
    }

    const int g = lane >> 2, tq = lane & 3;
#pragma unroll
    for (int mi = 0; mi < 4; mi++) {
        int row = warp_m * 64 + mi * 16 + g;
#pragma unroll
        for (int nj = 0; nj < 4; nj++) {
            int col = n0 + warp_n * 32 + nj * 8 + 2 * tq;
            *(float2*)(dst + (size_t)row * ldc + col) = make_float2(acc[mi][nj][0], acc[mi][nj][1]);
            *(float2*)(dst + (size_t)(row + 8) * ldc + col) = make_float2(acc[mi][nj][2], acc[mi][nj][3]);
        }
    }
}

// ---------------- recurrence tails (L2-coherent reads) ----------------
__device__ void z_tail(const float* __restrict__ noise, float* __restrict__ out,
                       int t, int cta) {
    int par = t % 3;
    __nv_bfloat16* aqx = gAqx3[par];
    for (int i4 = cta * 256 + threadIdx.x; i4 < Bb * Ll / 4; i4 += REC_CTAS * 256) {
        int m = i4 >> 6;
        int l = (i4 & 63) << 2;
        const int r = m * 1024;
#define SUM6(off) ({ \
        float4 s = *(const float4*)(g_bias_pq + (off)); \
        _Pragma("unroll") \
        for (int sg = 0; sg < 6; sg++) { \
            float4 a = __ldcg((const float4*)(&g_pqp[sg][0] + r + (off))); \
            s.x += a.x; s.y += a.y; s.z += a.z; s.w += a.w; \
        } s; })
        float4 qmu = SUM6(l);
        float4 qsig = SUM6(256 + l);
        float4 pmu = SUM6(512 + l);
        float4 psig = SUM6(768 + l);
#undef SUM6
        size_t o = ((size_t)t * Bb + m) * Ll + l;
        *(float4*)(out + OFF_QMU + o) = qmu;
        *(float4*)(out + OFF_QSIG + o) = qsig;
        *(float4*)(out + OFF_PMU + o) = pmu;
        *(float4*)(out + OFF_PSIG + o) = psig;
        float4 nz = *(const float4*)(noise + ((size_t)m * Tt + t) * Ll + l);
        float4 z = make_float4(nz.x * qsig.x + qmu.x, nz.y * qsig.y + qmu.y,
                               nz.z * qsig.z + qmu.z, nz.w * qsig.w + qmu.w);
        unsigned long long hi, lo;
        cvt4(z, hi, lo);
        int kg = 512 + l;
        st8(gAg + ipos(kg, m), hi);
        st8(gAg + ipos(kg + 1280, m), hi);
        st8(gAg + ipos(kg + 2560, m), lo);
        st8(aqx + qpos(l, m, 0), hi);
        st8(aqx + qpos(l, m, 1), lo);
    }
}

__device__ void lstm_tail(int t_next, int cta) {
    int par = t_next % 3;
    __nv_bfloat16* aqx = gAqx3[par];
    for (int i4 = cta * 256 + threadIdx.x; i4 < Bb * Hh / 4; i4 += REC_CTAS * 256) {
        int b = i4 >> 7;
        int n = (i4 & 127) << 2;
        const int r = b * 2048;
#define GSUM(off) ({ \
        float4 a = __ldcg((const float4*)(&g_gp[0][0] + r + (off))); \
        float4 x = __ldcg((const float4*)(&g_gp[1][0] + r + (off))); \
        float4 c = __ldcg((const float4*)(&g_gp[2][0] + r + (off))); \
        float4 d = *(const float4*)(g_bsum + (off)); \
        make_float4(a.x + x.x + c.x + d.x, a.y + x.y + c.y + d.y, \
                    a.z + x.z + c.z + d.z, a.w + x.w + c.w + d.w); })
        float4 gi = GSUM(n);
        float4 gf = GSUM(512 + n);
        float4 gg = GSUM(1024 + n);
        float4 go = GSUM(1536 + n);
#undef GSUM
        float4 co = *(const float4*)(g_c + b * 512 + n);
        float4 cn, h;
        cn.x = sigf(gf.x) * co.x + sigf(gi.x) * tanhf(gg.x);
        cn.y = sigf(gf.y) * co.y + sigf(gi.y) * tanhf(gg.y);
        cn.z = sigf(gf.z) * co.z + sigf(gi.z) * tanhf(gg.z);
        cn.w = sigf(gf.w) * co.w + sigf(gi.w) * tanhf(gg.w);
        h.x = sigf(go.x) * tanhf(cn.x);
        h.y = sigf(go.y) * tanhf(cn.y);
        h.z = sigf(go.z) * tanhf(cn.z);
        h.w = sigf(go.w) * tanhf(cn.w);
        *(float4*)(g_c + b * 512 + n) = cn;
        unsigned long long hi, lo;
        cvt4(h, hi, lo);
        int k = 512 + n;
        st8(gApq + ipos(k, b), hi);
        st8(gApq + ipos(k + 1024, b), hi);
        st8(gApq + ipos(k + 2048, b), lo);
        int kg = 768 + n;
        st8(gAg + ipos(kg, b), hi);
        st8(gAg + ipos(kg + 1280, b), hi);
        st8(gAg + ipos(kg + 2560, b), lo);
        int kq = 256 + n;
        st8(aqx + qpos(kq, b, 0), hi);
        st8(aqx + qpos(kq, b, 1), lo);
    }
    if (t_next < Tt) {
        const float* src = g_emb + (((size_t)t_next * Bb) << 9);
        for (int i4 = cta * 256 + threadIdx.x; i4 < Bb * Ee / 4; i4 += REC_CTAS * 256) {
            int m = i4 >> 7;
            int e = (i4 & 127) << 2;
            float4 v = *(const float4*)(src + ((size_t)m << 9) + e);
            unsigned long long hi, lo;
            cvt4(v, hi, lo);
            st8(gApq + ipos(e, m), hi);
            st8(gApq + ipos(e + 1024, m), hi);
            st8(gApq + ipos(e + 2048, m), lo);
            st8(gAg + ipos(e, m), hi);
            st8(gAg + ipos(e + 1280, m), hi);
            st8(gAg + ipos(e + 2560, m), lo);
        }
    }
}

// ---------------- qx GEMM body (128x192, unfolded, 2-stage) ----------------
#define STAGE_A2 (256 * PITCH)
#define QSTG ((256 + 384) * PITCH)
#define SMQX (2 * QSTG)            // 184320

__device__ __forceinline__ void load_stage_qx(uint32_t st, const char* srcA, const char* srcB,
                                              int tid) {
#pragma unroll
    for (int j = 0; j < 8; j++) {
        int i = tid + j * 256;
        cpasync16(st + (i >> 3) * PITCH + (i & 7) * 16, srcA + i * 16);
    }
#pragma unroll
    for (int j = 0; j < 12; j++) {
        int i = tid + j * 256;
        cpasync16(st + STAGE_A2 + (i >> 3) * PITCH + (i & 7) * 16, srcB + i * 16);
    }
    asm volatile("cp.async.commit_group;" ::: "memory");
}

__device__ void qx_gemm(int tile, int par, const float* __restrict__ qx_b,
                        float* __restrict__ dst, char* smem) {
    const uint32_t sb = s2u(smem);
    const int tid = threadIdx.x;
    const int wid = tid >> 5;
    const int lane = tid & 31;
    const int warp_m = wid >> 2;
    const int warp_n = wid & 3;
    const int n0 = tile * QROWS;

    const char* gA = (const char*)gAqx3[par];
    const char* gB = (const char*)(gBqx + (size_t)tile * (QCH * 2 * QROWS * 64));

    float acc[4][6][4];
#pragma unroll
    for (int i = 0; i < 4; i++)
#pragma unroll
        for (int j = 0; j < 6; j++)
#pragma unroll
            for (int q = 0; q < 4; q++) acc[i][j][q] = 0.0f;

    const int a_row = lane & 15;
    const int a_coff = (lane >> 4) << 4;
    const int b_row = ((lane >> 4) << 3) | (lane & 7);
    const int b_coff = ((lane >> 3) & 1) << 4;

    load_stage_qx(sb, gA, gB, tid);
    load_stage_qx(sb + QSTG, gA + 32768, gB + 49152, tid);

    for (int c = 0; c < QCH; c++) {
        asm volatile("cp.async.wait_group 1;" ::: "memory");
        __syncthreads();

        const uint32_t As = sb + (c & 1) * QSTG;
        const uint32_t Bs = As + STAGE_A2;
#pragma unroll
        for (int ks = 0; ks < 4; ks++) {
            uint32_t ah[4][4], al[4][4];
#pragma unroll
            for (int mi = 0; mi < 4; mi++) {
                uint32_t ar = (uint32_t)(warp_m * 64 + mi * 16 + a_row);
                ldmatrix_x4(ah[mi], As + ar * PITCH + ks * 32 + a_coff);
                ldmatrix_x4(al[mi], As + (ar + 128) * PITCH + ks * 32 + a_coff);
            }
#pragma unroll
            for (int jp = 0; jp < 3; jp++) {
                uint32_t bh[4], bl[4];
                uint32_t br = (uint32_t)(warp_n * 48 + jp * 16 + b_row);
                ldmatrix_x4(bh, Bs + br * PITCH + ks * 32 + b_coff);
                ldmatrix_x4(bl, Bs + (br + 192) * PITCH + ks * 32 + b_coff);
#pragma unroll
                for (int mi = 0; mi < 4; mi++) {
                    mma16816(acc[mi][jp * 2 + 0], ah[mi], bh[0], bh[1]);
                    mma16816(acc[mi][jp * 2 + 1], ah[mi], bh[2], bh[3]);
                    mma16816(acc[mi][jp * 2 + 0], al[mi], bh[0], bh[1]);
                    mma16816(acc[mi][jp * 2 + 1], al[mi], bh[2], bh[3]);
                    mma16816(acc[mi][jp * 2 + 0], ah[mi], bl[0], bl[1]);
                    mma16816(acc[mi][jp * 2 + 1], ah[mi], bl[2], bl[3]);
                }
            }
        }
        __syncthreads();
        if (c + 2 < QCH)
            load_stage_qx(sb + (c & 1) * QSTG, gA + (size_t)(c + 2) * 32768,
                          gB + (size_t)(c + 2) * 49152, tid);
        else
            asm volatile("cp.async.commit_group;" ::: "memory");
    }

    const int g = lane >> 2, tq = lane & 3;
#pragma unroll
    for (int mi = 0; mi < 4; mi++) {
        int row = warp_m * 64 + mi * 16 + g;
#pragma unroll
        for (int nj = 0; nj < 6; nj++) {
            int col = n0 + warp_n * 48 + nj * 8 + 2 * tq;
            if (col >= Vv) continue;
            float b0 = qx_b[col], b1 = qx_b[col + 1];
            *(float2*)(dst + (size_t)row * Vv + col) =
                make_float2(acc[mi][nj][0] + b0, acc[mi][nj][1] + b1);
            *(float2*)(dst + (size_t)(row + 8) * Vv + col) =
                make_float2(acc[mi][nj][2] + b0, acc[mi][nj][3] + b1);
        }
    }
}

// log-softmax over one row (256 threads)
__device__ void softmax_row(float* __restrict__ x) {
    __shared__ float sred[8];
    __shared__ float sval;
    const int tid = threadIdx.x;
    float m = -3.4e38f;
    for (int i = tid; i < Vv; i += 256) m = fmaxf(m, x[i]);
#pragma unroll
    for (int o = 16; o; o >>= 1) m = fmaxf(m, __shfl_xor_sync(0xffffffffu, m, o));
    if ((tid & 31) == 0) sred[tid >> 5] = m;
    __syncthreads();
    if (tid < 32) {
        float v = (tid < 8) ? sred[tid] : -3.4e38f;
#pragma unroll
        for (int o = 4; o; o >>= 1) v = fmaxf(v, __shfl_xor_sync(0xffffffffu, v, o));
        if (tid == 0) sval = v;
    }
    __syncthreads();
    m = sval;
    float s = 0.0f;
    for (int i = tid; i < Vv; i += 256) s += expf(x[i] - m);
#pragma unroll
    for (int o = 16; o; o >>= 1) s += __shfl_xor_sync(0xffffffffu, s, o);
    __syncthreads();
    if ((tid & 31) == 0) sred[tid >> 5] = s;
    __syncthreads();
    if (tid < 32) {
        float v = (tid < 8) ? sred[tid] : 0.0f;
#pragma unroll
        for (int o = 4; o; o >>= 1) v += __shfl_xor_sync(0xffffffffu, v, o);
        if (tid == 0) sval = m + logf(v);
    }
    __syncthreads();
    float lz = sval;
    for (int i = tid; i < Vv; i += 256) x[i] -= lz;
    __syncthreads();
}

// ---------------- persistent mega-kernel ----------------
__global__ void __launch_bounds__(256) mega_kernel(const float* __restrict__ features,
                                                   const float* __restrict__ noise,
                                                   const float* __restrict__ qx_b,
                                                   float* __restrict__ out) {
    extern __shared__ __align__(16) char smem[];
    const int cta = blockIdx.x;
    const int tid = threadIdx.x;

    if (cta < REC_CTAS) {
        // ----- recurrence group -----
        // prologue: feature image -> gates GEMM -> lstm tail (t=0 images)
        for (int i4 = cta * 256 + tid; i4 < Bb * Ee / 4; i4 += REC_CTAS * 256) {
            int m = i4 >> 7;
            int e = (i4 & 127) << 2;
            float4 v = *(const float4*)(features + ((size_t)m << 9) + e);
            unsigned long long hi, lo;
            cvt4(v, hi, lo);
            st8(gAg + ipos(e, m), hi);
            st8(gAg + ipos(e + 1280, m), hi);
            st8(gAg + ipos(e + 2560, m), lo);
        }
        bar48(&g_bar[Tt][0]);
        {
            int seg = cta >> 4, tile = cta & 15;
            gemm_body(gAg + (size_t)seg * 20 * 8192,
                      gBg + ((size_t)tile * NCH_G + seg * 20) * 8192,
                      20, g_gp[seg], 2048, tile << 7, smem);
        }
        bar48(&g_bar[Tt][1]);
        lstm_tail(0, cta);
        bar48(&g_bar[Tt][2]);

        for (int t = 0; t < Tt; t++) {
            {
                int seg = cta >> 3, tile = cta & 7;
                gemm_body(gApq + (size_t)seg * 8 * 8192,
                          gBpq + ((size_t)tile * NCH_PQ + seg * 8) * 8192,
                          8, g_pqp[seg], 1024, tile << 7, smem);
            }
            bar48(&g_bar[t][0]);
            if (t >= 3) waitflag(&g_flagQ[t - 3], QX_CTAS);
            z_tail(noise, out, t, cta);
            setflag(&g_flagZ[t]);
            bar48(&g_bar[t][1]);
            {
                int seg = cta >> 4, tile = cta & 15;
                gemm_body(gAg + (size_t)seg * 20 * 8192,
                          gBg + ((size_t)tile * NCH_G + seg * 20) * 8192,
                          20, g_gp[seg], 2048, tile << 7, smem);
            }
            bar48(&g_bar[t][2]);
            if (t >= 2) waitflag(&g_flagQ[t - 2], QX_CTAS);
            lstm_tail(t + 1, cta);
            bar48(&g_bar[t][3]);
        }
    } else if (cta < TOT_CTAS) {
        // ----- qx + softmax group -----
        int tile = cta - REC_CTAS;
        for (int t = 0; t < Tt; t++) {
            waitflag(&g_flagZ[t], REC_CTAS);
            float* qx_dst = out + OFF_QX + (size_t)t * Bb * Vv;
            qx_gemm(tile, t % 3, qx_b, qx_dst, smem);
            setflag(&g_flagQ[t]);
            waitflag(&g_flagQ[t], QX_CTAS);
            softmax_row(qx_dst + (size_t)tile * Vv);
            if (tile + QX_CTAS < Bb)
                softmax_row(qx_dst + (size_t)(tile + QX_CTAS) * Vv);
        }
    }
}

extern "C" void kernel_launch(void* const* d_in, const int* in_sizes, int n_in,
                              void* d_out, int out_size) {
    const float* features = (const float*)d_in[0];
    const int* captions = (const int*)d_in[1];
    const float* noise   = (const float*)d_in[3];
    const float* embed_W = (const float*)d_in[4];
    const float* W_ih    = (const float*)d_in[5];
    const float* W_hh    = (const float*)d_in[6];
    const float* b_ih    = (const float*)d_in[7];
    const float* b_hh    = (const float*)d_in[8];
    const float* qz_W    = (const float*)d_in[9];
    const float* qz_b    = (const float*)d_in[10];
    const float* prior_W = (const float*)d_in[11];
    const float* prior_b = (const float*)d_in[12];
    const float* qx_W    = (const float*)d_in[13];
    const float* qx_b    = (const float*)d_in[14];
    float* out = (float*)d_out;

    cudaFuncSetAttribute(mega_kernel, cudaFuncAttributeMaxDynamicSharedMemorySize, SMQX);

    // one-time prep (re-runs every replay; zeroes flags/barriers/c and gAg z,h sections)
    prep_misc_kernel<<<(PREP_MISC_TOT + 255) / 256, 256>>>(b_ih, b_hh, qz_b, prior_b,
                                                           embed_W, captions);
    prep_wg_kernel<<<(2048 * 320 + 255) / 256, 256>>>(W_ih, W_hh);
    prep_wpq_kernel<<<(1024 * 256 + 255) / 256, 256>>>(qz_W, prior_W);
    prep_wqx_kernel<<<(16128 * 192 + 255) / 256, 256>>>(qx_W);

    // the whole recurrence + qx + softmax in one persistent launch
    mega_kernel<<<TOT_CTAS, 256, SMQX>>>(features, noise, qx_b, out);
}

// round 11
// speedup vs baseline: 1.5079x; 1.5079x over previous
#include <cuda_runtime.h>
#include <cuda_bf16.h>
#include <cuda_fp16.h>
#include <math.h>
#include <stdint.h>

// Problem constants
#define Bb 128
#define Tt 32
#define Ee 512
#define Hh 512
#define Ll 256
#define Vv 16000

#define NCH_G  60      // gates: K2=3840 (folded bf16)
#define NCH_PQ 48      // pq: K2=3072 (folded bf16)
#define QROWS  192
#define QCH    12      // qx chunks of 64 over K=768 (fp16 single)
#define REC_CTAS 64
#define QX_CTAS  84

// Output layout: p_mus, p_sigmas, q_mus, q_sigmas, q_xs
#define OFF_PMU  ((size_t)0)
#define OFF_PSIG ((size_t)Tt * Bb * Ll)
#define OFF_QMU  ((size_t)2 * Tt * Bb * Ll)
#define OFF_QSIG ((size_t)3 * Tt * Bb * Ll)
#define OFF_QX   ((size_t)4 * Tt * Bb * Ll)

// ---------------- device scratch ----------------
__device__ float g_emb[Tt * Bb * Ee];
__device__ float g_bsum[4 * Hh];
__device__ float g_bias_pq[1024];
__device__ float g_c[Bb * Hh];
__device__ float g_pqp[8][Bb * 1024];    // pq split-K partials (8 segs)
__device__ float g_gp[4][Bb * 2048];     // gates split-K partials (4 segs)
__device__ int g_ctrA[Tt];
__device__ int g_ctrB[Tt + 1];

// Weight images (once)
__device__ __align__(16) __nv_bfloat16 gBg[(size_t)16 * NCH_G * 8192];
__device__ __align__(16) __nv_bfloat16 gBpq[(size_t)8 * NCH_PQ * 8192];
__device__ __align__(16) __half gBqx[(size_t)QX_CTAS * QCH * QROWS * 64];   // fp16 single
// A images: pq/gates folded bf16 single; qx fp16 triple-buffered
__device__ __align__(16) __nv_bfloat16 gAg[NCH_G * 8192];
__device__ __align__(16) __nv_bfloat16 gApq[NCH_PQ * 8192];
__device__ __align__(16) __half gAqx3[3][QCH * 8192];

__device__ __forceinline__ float sigf(float x) { return 1.0f / (1.0f + expf(-x)); }

__device__ __forceinline__ uint32_t s2u(const void* p) {
    uint32_t a;
    asm("{ .reg .u64 t; cvta.to.shared.u64 t, %1; cvt.u32.u64 %0, t; }" : "=r"(a) : "l"(p));
    return a;
}
__device__ __forceinline__ void cpasync16(uint32_t dst, const void* src) {
    asm volatile("cp.async.cg.shared.global [%0], [%1], 16;"
                 :: "r"(dst), "l"(__cvta_generic_to_global(src)) : "memory");
}
__device__ __forceinline__ void ldmatrix_x4(uint32_t* r, uint32_t addr) {
    asm volatile("ldmatrix.sync.aligned.m8n8.x4.shared.b16 {%0,%1,%2,%3}, [%4];"
                 : "=r"(r[0]), "=r"(r[1]), "=r"(r[2]), "=r"(r[3]) : "r"(addr));
}
__device__ __forceinline__ void mma_bf16(float* c, const uint32_t* a, uint32_t b0, uint32_t b1) {
    asm volatile(
        "mma.sync.aligned.m16n8k16.row.col.f32.bf16.bf16.f32 "
        "{%0,%1,%2,%3}, {%4,%5,%6,%7}, {%8,%9}, {%0,%1,%2,%3};"
        : "+f"(c[0]), "+f"(c[1]), "+f"(c[2]), "+f"(c[3])
        : "r"(a[0]), "r"(a[1]), "r"(a[2]), "r"(a[3]), "r"(b0), "r"(b1));
}
__device__ __forceinline__ void mma_f16(float* c, const uint32_t* a, uint32_t b0, uint32_t b1) {
    asm volatile(
        "mma.sync.aligned.m16n8k16.row.col.f32.f16.f16.f32 "
        "{%0,%1,%2,%3}, {%4,%5,%6,%7}, {%8,%9}, {%0,%1,%2,%3};"
        : "+f"(c[0]), "+f"(c[1]), "+f"(c[2]), "+f"(c[3])
        : "r"(a[0]), "r"(a[1]), "r"(a[2]), "r"(a[3]), "r"(b0), "r"(b1));
}
__device__ __forceinline__ size_t ipos(int k2, int m) {      // bf16 folded images
    return (((size_t)(k2 >> 6) * 128 + m) << 6) + (k2 & 63);
}
__device__ __forceinline__ size_t qpos16(int k, int m) {     // fp16 qx A image
    return (size_t)(k >> 6) * 8192 + m * 64 + (k & 63);
}
__device__ __forceinline__ unsigned long long pk4(__nv_bfloat16 a, __nv_bfloat16 b,
                                                  __nv_bfloat16 c, __nv_bfloat16 d) {
    union { __nv_bfloat16 h[4]; unsigned long long u; } t;
    t.h[0] = a; t.h[1] = b; t.h[2] = c; t.h[3] = d;
    return t.u;
}
__device__ __forceinline__ void cvt4(float4 v, unsigned long long& hi, unsigned long long& lo) {
    __nv_bfloat16 h0 = __float2bfloat16(v.x), h1 = __float2bfloat16(v.y);
    __nv_bfloat16 h2 = __float2bfloat16(v.z), h3 = __float2bfloat16(v.w);
    hi = pk4(h0, h1, h2, h3);
    lo = pk4(__float2bfloat16(v.x - __bfloat162float(h0)),
             __float2bfloat16(v.y - __bfloat162float(h1)),
             __float2bfloat16(v.z - __bfloat162float(h2)),
             __float2bfloat16(v.w - __bfloat162float(h3)));
}
__device__ __forceinline__ unsigned long long cvt4h(float4 v) {
    union { __half2 h2[2]; unsigned long long u; } t;
    t.h2[0] = __floats2half2_rn(v.x, v.y);
    t.h2[1] = __floats2half2_rn(v.z, v.w);
    return t.u;
}
__device__ __forceinline__ void st8b(__nv_bfloat16* p, unsigned long long v) {
    *(unsigned long long*)p = v;
}
__device__ __forceinline__ void st8h(__half* p, unsigned long long v) {
    *(unsigned long long*)p = v;
}
// barrier across the 64 recurrence CTAs (per-step counter, prep-zeroed)
__device__ __forceinline__ void grid_barrier64(int* ctr) {
    __threadfence();
    __syncthreads();
    if (threadIdx.x == 0) {
        atomicAdd(ctr, 1);
        volatile int* v = ctr;
        while (*v < REC_CTAS) { }
    }
    __syncthreads();
}

// ---------------- one-time prep ----------------
#define N_EMB4 (Tt * Bb * Ee / 4)
#define GAG_Z  (NCH_G * 8192 * 2 / 16)
#define N_CTR  (2 * Tt + 1)
__global__ void prep_misc_kernel(const float* __restrict__ b_ih, const float* __restrict__ b_hh,
                                 const float* __restrict__ qz_b, const float* __restrict__ prior_b,
                                 const float* __restrict__ embed_W, const int* __restrict__ captions) {
    int i4 = blockIdx.x * blockDim.x + threadIdx.x;
    if (i4 < N_EMB4) {
        int j = i4 * 4;
        int tb = j >> 9, e = j & 511;
        int t = tb / Bb, b = tb % Bb;
        *(float4*)(g_emb + j) = *(const float4*)(embed_W + (size_t)captions[b * Tt + t] * Ee + e);
        return;
    }
    i4 -= N_EMB4;
    if (i4 < 512) {
        int n = i4 * 4;
        float4 a = *(const float4*)(b_ih + n), b = *(const float4*)(b_hh + n);
        *(float4*)(g_bsum + n) = make_float4(a.x + b.x, a.y + b.y, a.z + b.z, a.w + b.w);
        return;
    }
    i4 -= 512;
    if (i4 < 256) {
        int n = i4 * 4;
        *(float4*)(g_bias_pq + n) = (n < 512) ? *(const float4*)(qz_b + n)
                                              : *(const float4*)(prior_b + n - 512);
        return;
    }
    i4 -= 256;
    if (i4 < Bb * Hh / 4) { *(float4*)(g_c + i4 * 4) = make_float4(0, 0, 0, 0); return; }
    i4 -= Bb * Hh / 4;
    if (i4 < GAG_Z) { *(float4*)((char*)gAg + (size_t)i4 * 16) = make_float4(0, 0, 0, 0); return; }
    i4 -= GAG_Z;
    if (i4 < N_CTR) {
        if (i4 < Tt) g_ctrA[i4] = 0;
        else g_ctrB[i4 - Tt] = 0;
    }
}
#define PREP_MISC_TOT (N_EMB4 + 512 + 256 + Bb * Hh / 4 + GAG_Z + N_CTR)

// gates weights: N=2048, K order [e(512), z(256), h(512)], fold [hi|lo|hi]
__global__ void prep_wg_kernel(const float* __restrict__ W_ih, const float* __restrict__ W_hh) {
    int idx = blockIdx.x * blockDim.x + threadIdx.x;
    if (idx >= 2048 * 320) return;
    int n = idx / 320, k = (idx - n * 320) * 4;
    float4 v = (k < 768) ? *(const float4*)(W_ih + (size_t)n * 768 + k)
                         : *(const float4*)(W_hh + (size_t)n * 512 + (k - 768));
    unsigned long long hi, lo;
    cvt4(v, hi, lo);
    int tile = n >> 7, row = n & 127;
    __nv_bfloat16* base = gBg + (size_t)tile * NCH_G * 8192;
    st8b(base + ipos(k, row), hi);
    st8b(base + ipos(k + 1280, row), lo);
    st8b(base + ipos(k + 2560, row), hi);
}

// pq weights: N=1024 (qz 0-511, prior 512-1023 padded over e), K order [e, h]
__global__ void prep_wpq_kernel(const float* __restrict__ qz_W, const float* __restrict__ prior_W) {
    int idx = blockIdx.x * blockDim.x + threadIdx.x;
    if (idx >= 1024 * 256) return;
    int n = idx >> 8, k = (idx & 255) << 2;
    float4 v;
    if (n < 512) v = *(const float4*)(qz_W + (size_t)n * 1024 + k);
    else if (k < 512) v = make_float4(0, 0, 0, 0);
    else v = *(const float4*)(prior_W + (size_t)(n - 512) * 512 + (k - 512));
    unsigned long long hi, lo;
    cvt4(v, hi, lo);
    int tile = n >> 7, row = n & 127;
    __nv_bfloat16* base = gBpq + (size_t)tile * NCH_PQ * 8192;
    st8b(base + ipos(k, row), hi);
    st8b(base + ipos(k + 1024, row), lo);
    st8b(base + ipos(k + 2048, row), hi);
}

// qx weights fp16 single: [tile 84][chunk 12][192 x 64]
__global__ void prep_wqx_kernel(const float* __restrict__ qx_W) {
    int idx = blockIdx.x * blockDim.x + threadIdx.x;
    if (idx >= 16128 * 192) return;
    int n = idx / 192, k = (idx - n * 192) * 4;
    float4 v = (n < Vv) ? *(const float4*)(qx_W + (size_t)n * 768 + k)
                        : make_float4(0, 0, 0, 0);
    int tile = n / QROWS, row = n - tile * QROWS;
    __half* base = gBqx + (size_t)tile * (QCH * QROWS * 64);
    st8h(base + (size_t)(k >> 6) * (QROWS * 64) + row * 64 + (k & 63), cvt4h(v));
}

// features A-image (initial step): e-section of gAg (z,h sections pre-zeroed)
__global__ void build_feat_kernel(const float* __restrict__ features) {
    int i4 = blockIdx.x * 512 + threadIdx.x;
    int m = i4 >> 7;
    int e = (i4 & 127) << 2;
    float4 v = *(const float4*)(features + (size_t)m * 512 + e);
    unsigned long long hi, lo;
    cvt4(v, hi, lo);
    st8b(gAg + ipos(e, m), hi);
    st8b(gAg + ipos(e + 1280, m), hi);
    st8b(gAg + ipos(e + 2560, m), lo);
}

// ---------------- folded bf16 GEMM body (pq/gates; 128x128 tiles, 3-stage) ----------------
#define PITCH 144
#define STAGE_B 18432
#define SSZ128 ((128 + 128) * PITCH)
#define SM128 (3 * SSZ128)

__device__ __forceinline__ void load_stage(uint32_t st, const char* srcA, const char* srcB, int tid) {
#pragma unroll
    for (int j = 0; j < 4; j++) {
        int i = tid + j * 256;
        cpasync16(st + (i >> 3) * PITCH + (i & 7) * 16, srcA + i * 16);
    }
#pragma unroll
    for (int j = 0; j < 4; j++) {
        int i = tid + j * 256;
        cpasync16(st + STAGE_B + (i >> 3) * PITCH + (i & 7) * 16, srcB + i * 16);
    }
    asm volatile("cp.async.commit_group;" ::: "memory");
}

__device__ __forceinline__ void gemm_body(
    const __nv_bfloat16* __restrict__ Aimg, const __nv_bfloat16* __restrict__ Bimg,
    int nchunk, float* __restrict__ dst, int ldc, int n0) {
    extern __shared__ __align__(16) char smem[];
    const uint32_t sb = s2u(smem);
    const int tid = threadIdx.x;
    const int wid = tid >> 5;
    const int lane = tid & 31;
    const int warp_m = wid >> 2;
    const int warp_n = wid & 3;

    const char* gA = (const char*)Aimg;
    const char* gB = (const char*)Bimg;

    float acc[4][4][4];
#pragma unroll
    for (int i = 0; i < 4; i++)
#pragma unroll
        for (int j = 0; j < 4; j++)
#pragma unroll
            for (int q = 0; q < 4; q++) acc[i][j][q] = 0.0f;

    const int a_row = lane & 15;
    const int a_coff = (lane >> 4) << 4;
    const int b_row = ((lane >> 4) << 3) | (lane & 7);
    const int b_coff = ((lane >> 3) & 1) << 4;

#pragma unroll
    for (int s = 0; s < 3; s++)
        load_stage(sb + s * SSZ128, gA + (size_t)s * 16384, gB + (size_t)s * 16384, tid);

    int slot = 0;
    for (int c = 0; c < nchunk; c++) {
        asm volatile("cp.async.wait_group 2;" ::: "memory");
        __syncthreads();

        const uint32_t As = sb + slot * SSZ128;
        const uint32_t Bs = As + STAGE_B;
#pragma unroll
        for (int ks = 0; ks < 4; ks++) {
            uint32_t a[4][4];
#pragma unroll
            for (int mi = 0; mi < 4; mi++)
                ldmatrix_x4(a[mi], As + (uint32_t)(warp_m * 64 + mi * 16 + a_row) * PITCH +
                                    ks * 32 + a_coff);
#pragma unroll
            for (int jp = 0; jp < 2; jp++) {
                uint32_t b[4];
                ldmatrix_x4(b, Bs + (uint32_t)(warp_n * 32 + jp * 16 + b_row) * PITCH +
                                ks * 32 + b_coff);
#pragma unroll
                for (int mi = 0; mi < 4; mi++) {
                    mma_bf16(acc[mi][jp * 2 + 0], a[mi], b[0], b[1]);
                    mma_bf16(acc[mi][jp * 2 + 1], a[mi], b[2], b[3]);
                }
            }
        }
        __syncthreads();
        if (c + 3 < nchunk)
            load_stage(sb + slot * SSZ128, gA + (size_t)(c + 3) * 16384,
                       gB + (size_t)(c + 3) * 16384, tid);
        else
            asm volatile("cp.async.commit_group;" ::: "memory");
        slot = (slot == 2) ? 0 : slot + 1;
    }

    const int g = lane >> 2, tq = lane & 3;
#pragma unroll
    for (int mi = 0; mi < 4; mi++) {
        int row = warp_m * 64 + mi * 16 + g;
#pragma unroll
        for (int nj = 0; nj < 4; nj++) {
            int col = n0 + warp_n * 32 + nj * 8 + 2 * tq;
            *(float2*)(dst + (size_t)row * ldc + col) = make_float2(acc[mi][nj][0], acc[mi][nj][1]);
            *(float2*)(dst + (size_t)(row + 8) * ldc + col) = make_float2(acc[mi][nj][2], acc[mi][nj][3]);
        }
    }
}

// ---------------- fused pq GEMM + reduce/z/outputs (64 CTAs; 8 segs x 8 tiles) ----------------
__global__ void __launch_bounds__(256) pqz_kernel(const float* __restrict__ noise,
                                                  float* __restrict__ out, int t) {
    int seg = blockIdx.x >> 3, tile = blockIdx.x & 7;
    gemm_body(gApq + (size_t)seg * 6 * 8192,
              gBpq + ((size_t)tile * NCH_PQ + seg * 6) * 8192,
              6, g_pqp[seg], 1024, tile << 7);

    grid_barrier64(&g_ctrA[t]);

    __half* aqx = gAqx3[t % 3];
    for (int i4 = blockIdx.x * 256 + threadIdx.x; i4 < Bb * Ll / 4; i4 += REC_CTAS * 256) {
        int m = i4 >> 6;
        int l = (i4 & 63) << 2;
        const int r = m * 1024;
#define SUM8(off) ({ \
        float4 s = *(const float4*)(g_bias_pq + (off)); \
        _Pragma("unroll") \
        for (int sg = 0; sg < 8; sg++) { \
            float4 a = __ldcg((const float4*)(&g_pqp[sg][0] + r + (off))); \
            s.x += a.x; s.y += a.y; s.z += a.z; s.w += a.w; \
        } s; })
        float4 qmu = SUM8(l);
        float4 qsig = SUM8(256 + l);
        float4 pmu = SUM8(512 + l);
        float4 psig = SUM8(768 + l);
#undef SUM8
        size_t o = ((size_t)t * Bb + m) * Ll + l;
        *(float4*)(out + OFF_QMU + o) = qmu;
        *(float4*)(out + OFF_QSIG + o) = qsig;
        *(float4*)(out + OFF_PMU + o) = pmu;
        *(float4*)(out + OFF_PSIG + o) = psig;
        float4 nz = *(const float4*)(noise + ((size_t)m * Tt + t) * Ll + l);
        float4 z = make_float4(nz.x * qsig.x + qmu.x, nz.y * qsig.y + qmu.y,
                               nz.z * qsig.z + qmu.z, nz.w * qsig.w + qmu.w);
        unsigned long long hi, lo;
        cvt4(z, hi, lo);
        int kg = 512 + l;
        st8b(gAg + ipos(kg, m), hi);
        st8b(gAg + ipos(kg + 1280, m), hi);
        st8b(gAg + ipos(kg + 2560, m), lo);
        st8h(aqx + qpos16(l, m), cvt4h(z));
    }
}

// ---------------- fused gates GEMM + LSTM + h/e-images (64 CTAs; 4 segs x 16 tiles) ----------------
__global__ void __launch_bounds__(256) gatesepi_kernel(int t_next) {
    int seg = blockIdx.x >> 4, tile = blockIdx.x & 15;
    gemm_body(gAg + (size_t)seg * 15 * 8192,
              gBg + ((size_t)tile * NCH_G + seg * 15) * 8192,
              15, g_gp[seg], 2048, tile << 7);

    grid_barrier64(&g_ctrB[t_next]);

    __half* aqx = gAqx3[t_next % 3];
    for (int i4 = blockIdx.x * 256 + threadIdx.x; i4 < Bb * Hh / 4; i4 += REC_CTAS * 256) {
        int b = i4 >> 7;
        int n = (i4 & 127) << 2;
        const int r = b * 2048;
#define GSUM(off) ({ \
        float4 s = *(const float4*)(g_bsum + (off)); \
        _Pragma("unroll") \
        for (int sg = 0; sg < 4; sg++) { \
            float4 a = __ldcg((const float4*)(&g_gp[sg][0] + r + (off))); \
            s.x += a.x; s.y += a.y; s.z += a.z; s.w += a.w; \
        } s; })
        float4 gi = GSUM(n);
        float4 gf = GSUM(512 + n);
        float4 gg = GSUM(1024 + n);
        float4 go = GSUM(1536 + n);
#undef GSUM
        float4 co = *(const float4*)(g_c + b * 512 + n);
        float4 cn, h;
        cn.x = sigf(gf.x) * co.x + sigf(gi.x) * tanhf(gg.x);
        cn.y = sigf(gf.y) * co.y + sigf(gi.y) * tanhf(gg.y);
        cn.z = sigf(gf.z) * co.z + sigf(gi.z) * tanhf(gg.z);
        cn.w = sigf(gf.w) * co.w + sigf(gi.w) * tanhf(gg.w);
        h.x = sigf(go.x) * tanhf(cn.x);
        h.y = sigf(go.y) * tanhf(cn.y);
        h.z = sigf(go.z) * tanhf(cn.z);
        h.w = sigf(go.w) * tanhf(cn.w);
        *(float4*)(g_c + b * 512 + n) = cn;
        unsigned long long hi, lo;
        cvt4(h, hi, lo);
        int k = 512 + n;
        st8b(gApq + ipos(k, b), hi);
        st8b(gApq + ipos(k + 1024, b), hi);
        st8b(gApq + ipos(k + 2048, b), lo);
        int kg = 768 + n;
        st8b(gAg + ipos(kg, b), hi);
        st8b(gAg + ipos(kg + 1280, b), hi);
        st8b(gAg + ipos(kg + 2560, b), lo);
        st8h(aqx + qpos16(256 + n, b), cvt4h(h));
    }
    if (t_next < Tt) {
        const float* src = g_emb + (((size_t)t_next * Bb) << 9);
        for (int i4 = blockIdx.x * 256 + threadIdx.x; i4 < Bb * Ee / 4; i4 += REC_CTAS * 256) {
            int m = i4 >> 7;
            int e = (i4 & 127) << 2;
            float4 v = *(const float4*)(src + ((size_t)m << 9) + e);
            unsigned long long hi, lo;
            cvt4(v, hi, lo);
            st8b(gApq + ipos(e, m), hi);
            st8b(gApq + ipos(e + 1024, m), hi);
            st8b(gApq + ipos(e + 2048, m), lo);
            st8b(gAg + ipos(e, m), hi);
            st8b(gAg + ipos(e + 1280, m), hi);
            st8b(gAg + ipos(e + 2560, m), lo);
        }
    }
}

// ---------------- fp16 single-product qx GEMM (84 CTAs, 128x192, 3-stage) ----------------
#define STAGE_A16 (128 * PITCH)             // 18432
#define QSTG ((128 + 192) * PITCH)          // 46080
#define SMQX (3 * QSTG)                     // 138240

__device__ __forceinline__ void load_stage_qx(uint32_t st, const char* srcA, const char* srcB,
                                              int tid) {
#pragma unroll
    for (int j = 0; j < 4; j++) {          // A: 16KB (128 rows x 128B)
        int i = tid + j * 256;
        cpasync16(st + (i >> 3) * PITCH + (i & 7) * 16, srcA + i * 16);
    }
#pragma unroll
    for (int j = 0; j < 6; j++) {          // B: 24KB (192 rows x 128B)
        int i = tid + j * 256;
        cpasync16(st + STAGE_A16 + (i >> 3) * PITCH + (i & 7) * 16, srcB + i * 16);
    }
    asm volatile("cp.async.commit_group;" ::: "memory");
}

__global__ void __launch_bounds__(256) qx_kernel(const float* __restrict__ qx_b,
                                                 float* __restrict__ dst, int par) {
    extern __shared__ __align__(16) char smem[];
    const uint32_t sb = s2u(smem);
    const int tid = threadIdx.x;
    const int wid = tid >> 5;
    const int lane = tid & 31;
    const int warp_m = wid >> 2;
    const int warp_n = wid & 3;
    const int n0 = blockIdx.x * QROWS;

    const char* gA = (const char*)gAqx3[par];
    const char* gB = (const char*)(gBqx + (size_t)blockIdx.x * (QCH * QROWS * 64));

    float acc[4][6][4];
#pragma unroll
    for (int i = 0; i < 4; i++)
#pragma unroll
        for (int j = 0; j < 6; j++)
#pragma unroll
            for (int q = 0; q < 4; q++) acc[i][j][q] = 0.0f;

    const int a_row = lane & 15;
    const int a_coff = (lane >> 4) << 4;
    const int b_row = ((lane >> 4) << 3) | (lane & 7);
    const int b_coff = ((lane >> 3) & 1) << 4;

#pragma unroll
    for (int s = 0; s < 3; s++)
        load_stage_qx(sb + s * QSTG, gA + (size_t)s * 16384, gB + (size_t)s * 24576, tid);

    int slot = 0;
    for (int c = 0; c < QCH; c++) {
        asm volatile("cp.async.wait_group 2;" ::: "memory");
        __syncthreads();

        const uint32_t As = sb + slot * QSTG;
        const uint32_t Bs = As + STAGE_A16;
#pragma unroll
        for (int ks = 0; ks < 4; ks++) {
            uint32_t a[4][4];
#pragma unroll
            for (int mi = 0; mi < 4; mi++)
                ldmatrix_x4(a[mi], As + (uint32_t)(warp_m * 64 + mi * 16 + a_row) * PITCH +
                                    ks * 32 + a_coff);
#pragma unroll
            for (int jp = 0; jp < 3; jp++) {
                uint32_t b[4];
                ldmatrix_x4(b, Bs + (uint32_t)(warp_n * 48 + jp * 16 + b_row) * PITCH +
                                ks * 32 + b_coff);
#pragma unroll
                for (int mi = 0; mi < 4; mi++) {
                    mma_f16(acc[mi][jp * 2 + 0], a[mi], b[0], b[1]);
                    mma_f16(acc[mi][jp * 2 + 1], a[mi], b[2], b[3]);
                }
            }
        }
        __syncthreads();
        if (c + 3 < QCH)
            load_stage_qx(sb + slot * QSTG, gA + (size_t)(c + 3) * 16384,
                          gB + (size_t)(c + 3) * 24576, tid);
        else
            asm volatile("cp.async.commit_group;" ::: "memory");
        slot = (slot == 2) ? 0 : slot + 1;
    }

    const int g = lane >> 2, tq = lane & 3;
#pragma unroll
    for (int mi = 0; mi < 4; mi++) {
        int row = warp_m * 64 + mi * 16 + g;
#pragma unroll
        for (int nj = 0; nj < 6; nj++) {
            int col = n0 + warp_n * 48 + nj * 8 + 2 * tq;
            if (col >= Vv) continue;
            float b0 = qx_b[col], b1 = qx_b[col + 1];
            *(float2*)(dst + (size_t)row * Vv + col) =
                make_float2(acc[mi][nj][0] + b0, acc[mi][nj][1] + b1);
            *(float2*)(dst + (size_t)(row + 8) * Vv + col) =
                make_float2(acc[mi][nj][2] + b0, acc[mi][nj][3] + b1);
        }
    }
}

// In-place log_softmax over rows of length V
__global__ void softmax_kernel(float* __restrict__ base) {
    float* x = base + (size_t)blockIdx.x * Vv;
    __shared__ float sred[16];
    __shared__ float sval;
    const int tid = threadIdx.x;
    float m = -3.4e38f;
    for (int i = tid; i < Vv; i += 512) m = fmaxf(m, x[i]);
#pragma unroll
    for (int o = 16; o; o >>= 1) m = fmaxf(m, __shfl_xor_sync(0xffffffffu, m, o));
    if ((tid & 31) == 0) sred[tid >> 5] = m;
    __syncthreads();
    if (tid < 32) {
        float v = (tid < 16) ? sred[tid] : -3.4e38f;
#pragma unroll
        for (int o = 8; o; o >>= 1) v = fmaxf(v, __shfl_xor_sync(0xffffffffu, v, o));
        if (tid == 0) sval = v;
    }
    __syncthreads();
    m = sval;
    float s = 0.0f;
    for (int i = tid; i < Vv; i += 512) s += expf(x[i] - m);
#pragma unroll
    for (int o = 16; o; o >>= 1) s += __shfl_xor_sync(0xffffffffu, s, o);
    __syncthreads();
    if ((tid & 31) == 0) sred[tid >> 5] = s;
    __syncthreads();
    if (tid < 32) {
        float v = (tid < 16) ? sred[tid] : 0.0f;
#pragma unroll
        for (int o = 8; o; o >>= 1) v += __shfl_xor_sync(0xffffffffu, v, o);
        if (tid == 0) sval = m + logf(v);
    }
    __syncthreads();
    float lz = sval;
    for (int i = tid; i < Vv; i += 512) x[i] -= lz;
}

extern "C" void kernel_launch(void* const* d_in, const int* in_sizes, int n_in,
                              void* d_out, int out_size) {
    const float* features = (const float*)d_in[0];
    const int* captions = (const int*)d_in[1];
    const float* noise   = (const float*)d_in[3];
    const float* embed_W = (const float*)d_in[4];
    const float* W_ih    = (const float*)d_in[5];
    const float* W_hh    = (const float*)d_in[6];
    const float* b_ih    = (const float*)d_in[7];
    const float* b_hh    = (const float*)d_in[8];
    const float* qz_W    = (const float*)d_in[9];
    const float* qz_b    = (const float*)d_in[10];
    const float* prior_W = (const float*)d_in[11];
    const float* prior_b = (const float*)d_in[12];
    const float* qx_W    = (const float*)d_in[13];
    const float* qx_b    = (const float*)d_in[14];
    float* out = (float*)d_out;

    static cudaStream_t s1 = nullptr, s2 = nullptr;
    static cudaEvent_t evF = nullptr, evZ = nullptr, evQ[3] = {nullptr, nullptr, nullptr};
    static cudaEvent_t evW = nullptr, evJ1 = nullptr, evJ2 = nullptr;
    if (s1 == nullptr) {
        cudaStreamCreateWithFlags(&s1, cudaStreamNonBlocking);
        cudaStreamCreateWithFlags(&s2, cudaStreamNonBlocking);
        cudaEventCreateWithFlags(&evF, cudaEventDisableTiming);
        cudaEventCreateWithFlags(&evZ, cudaEventDisableTiming);
        for (int i = 0; i < 3; i++) cudaEventCreateWithFlags(&evQ[i], cudaEventDisableTiming);
        cudaEventCreateWithFlags(&evW, cudaEventDisableTiming);
        cudaEventCreateWithFlags(&evJ1, cudaEventDisableTiming);
        cudaEventCreateWithFlags(&evJ2, cudaEventDisableTiming);
    }

    cudaFuncSetAttribute(pqz_kernel, cudaFuncAttributeMaxDynamicSharedMemorySize, SM128);
    cudaFuncSetAttribute(gatesepi_kernel, cudaFuncAttributeMaxDynamicSharedMemorySize, SM128);
    cudaFuncSetAttribute(qx_kernel, cudaFuncAttributeMaxDynamicSharedMemorySize, SMQX);

    // one-time prep — fork side streams from the capture stream via an event
    prep_misc_kernel<<<(PREP_MISC_TOT + 255) / 256, 256>>>(b_ih, b_hh, qz_b, prior_b,
                                                           embed_W, captions);
    cudaEventRecord(evF, 0);
    cudaStreamWaitEvent(s1, evF, 0);
    cudaStreamWaitEvent(s2, evF, 0);
    prep_wqx_kernel<<<(16128 * 192 + 255) / 256, 256, 0, s1>>>(qx_W);   // ordered before qx on s1
    prep_wg_kernel<<<(2048 * 320 + 255) / 256, 256, 0, s2>>>(W_ih, W_hh);
    prep_wpq_kernel<<<(1024 * 256 + 255) / 256, 256>>>(qz_W, prior_W);
    cudaEventRecord(evW, s2);
    cudaStreamWaitEvent(0, evW, 0);   // gBg ready before gatesepi on stream 0

    // initial LSTM step: features through the gates tc path (z,h image sections are zero)
    build_feat_kernel<<<32, 512>>>(features);
    gatesepi_kernel<<<REC_CTAS, 256, SM128>>>(0);

    for (int t = 0; t < Tt; t++) {
        pqz_kernel<<<REC_CTAS, 256, SM128>>>(noise, out, t);
        cudaEventRecord(evZ, 0);
        cudaStreamWaitEvent(s1, evZ, 0);
        float* qx_dst = out + OFF_QX + (size_t)t * Bb * Vv;
        qx_kernel<<<QX_CTAS, 256, SMQX, s1>>>(qx_b, qx_dst, t % 3);
        cudaEventRecord(evQ[t % 3], s1);
        cudaStreamWaitEvent(s2, evQ[t % 3], 0);
        softmax_kernel<<<128, 512, 0, s2>>>(qx_dst);
        // gatesepi(t+1) writes qx A-buffer (t+1)%3, last read by qx(t-2)
        if (t >= 2) cudaStreamWaitEvent(0, evQ[(t + 1) % 3], 0);
        gatesepi_kernel<<<REC_CTAS, 256, SM128>>>(t + 1);
    }

    cudaEventRecord(evJ1, s1);
    cudaStreamWaitEvent(0, evJ1, 0);
    cudaEventRecord(evJ2, s2);
    cudaStreamWaitEvent(0, evJ2, 0);
}

// round 12
// speedup vs baseline: 1.6534x; 1.0965x over previous
#include <cuda_runtime.h>
#include <cuda_bf16.h>
#include <cuda_fp16.h>
#include <math.h>
#include <stdint.h>

// Problem constants
#define Bb 128
#define Tt 32
#define Ee 512
#define Hh 512
#define Ll 256
#define Vv 16000

#define NCH_G  60      // gates: K2=3840 (folded bf16)
#define NCH_PQ 48      // pq: K2=3072 (folded bf16)
#define QROWS  192
#define QCH    12      // qx chunks of 64 over K=768 (fp16 single)
#define REC_CTAS 64
#define QX_CTAS  84

// Output layout: p_mus, p_sigmas, q_mus, q_sigmas, q_xs
#define OFF_PMU  ((size_t)0)
#define OFF_PSIG ((size_t)Tt * Bb * Ll)
#define OFF_QMU  ((size_t)2 * Tt * Bb * Ll)
#define OFF_QSIG ((size_t)3 * Tt * Bb * Ll)
#define OFF_QX   ((size_t)4 * Tt * Bb * Ll)

// ---------------- device scratch ----------------
__device__ float g_emb[Tt * Bb * Ee];
__device__ float g_bsum[4 * Hh];
__device__ float g_bias_pq[1024];
__device__ float g_c[Bb * Hh];
__device__ float g_pqp[8][Bb * 1024];    // pq split-K partials (8 segs)
__device__ float g_gp[4][Bb * 2048];     // gates split-K partials (4 segs)
__device__ int g_ctrP;                   // prologue barrier
__device__ int g_bar3[Tt][3];            // rec_step internal barriers
__device__ int g_qctr[Tt];               // qx all-84 barriers

// Weight images (once)
__device__ __align__(16) __nv_bfloat16 gBg[(size_t)16 * NCH_G * 8192];
__device__ __align__(16) __nv_bfloat16 gBpq[(size_t)8 * NCH_PQ * 8192];
__device__ __align__(16) __half gBqx[(size_t)QX_CTAS * QCH * QROWS * 64];   // fp16 single
// A images: pq/gates folded bf16 single; qx fp16 triple-buffered
__device__ __align__(16) __nv_bfloat16 gAg[NCH_G * 8192];
__device__ __align__(16) __nv_bfloat16 gApq[NCH_PQ * 8192];
__device__ __align__(16) __half gAqx3[3][QCH * 8192];

__device__ __forceinline__ float sigf(float x) { return 1.0f / (1.0f + expf(-x)); }

__device__ __forceinline__ uint32_t s2u(const void* p) {
    uint32_t a;
    asm("{ .reg .u64 t; cvta.to.shared.u64 t, %1; cvt.u32.u64 %0, t; }" : "=r"(a) : "l"(p));
    return a;
}
__device__ __forceinline__ void cpasync16(uint32_t dst, const void* src) {
    asm volatile("cp.async.cg.shared.global [%0], [%1], 16;"
                 :: "r"(dst), "l"(__cvta_generic_to_global(src)) : "memory");
}
__device__ __forceinline__ void ldmatrix_x4(uint32_t* r, uint32_t addr) {
    asm volatile("ldmatrix.sync.aligned.m8n8.x4.shared.b16 {%0,%1,%2,%3}, [%4];"
                 : "=r"(r[0]), "=r"(r[1]), "=r"(r[2]), "=r"(r[3]) : "r"(addr));
}
__device__ __forceinline__ void mma_bf16(float* c, const uint32_t* a, uint32_t b0, uint32_t b1) {
    asm volatile(
        "mma.sync.aligned.m16n8k16.row.col.f32.bf16.bf16.f32 "
        "{%0,%1,%2,%3}, {%4,%5,%6,%7}, {%8,%9}, {%0,%1,%2,%3};"
        : "+f"(c[0]), "+f"(c[1]), "+f"(c[2]), "+f"(c[3])
        : "r"(a[0]), "r"(a[1]), "r"(a[2]), "r"(a[3]), "r"(b0), "r"(b1));
}
__device__ __forceinline__ void mma_f16(float* c, const uint32_t* a, uint32_t b0, uint32_t b1) {
    asm volatile(
        "mma.sync.aligned.m16n8k16.row.col.f32.f16.f16.f32 "
        "{%0,%1,%2,%3}, {%4,%5,%6,%7}, {%8,%9}, {%0,%1,%2,%3};"
        : "+f"(c[0]), "+f"(c[1]), "+f"(c[2]), "+f"(c[3])
        : "r"(a[0]), "r"(a[1]), "r"(a[2]), "r"(a[3]), "r"(b0), "r"(b1));
}
__device__ __forceinline__ size_t ipos(int k2, int m) {      // bf16 folded images
    return (((size_t)(k2 >> 6) * 128 + m) << 6) + (k2 & 63);
}
__device__ __forceinline__ size_t qpos16(int k, int m) {     // fp16 qx A image
    return (size_t)(k >> 6) * 8192 + m * 64 + (k & 63);
}
__device__ __forceinline__ unsigned long long pk4(__nv_bfloat16 a, __nv_bfloat16 b,
                                                  __nv_bfloat16 c, __nv_bfloat16 d) {
    union { __nv_bfloat16 h[4]; unsigned long long u; } t;
    t.h[0] = a; t.h[1] = b; t.h[2] = c; t.h[3] = d;
    return t.u;
}
__device__ __forceinline__ void cvt4(float4 v, unsigned long long& hi, unsigned long long& lo) {
    __nv_bfloat16 h0 = __float2bfloat16(v.x), h1 = __float2bfloat16(v.y);
    __nv_bfloat16 h2 = __float2bfloat16(v.z), h3 = __float2bfloat16(v.w);
    hi = pk4(h0, h1, h2, h3);
    lo = pk4(__float2bfloat16(v.x - __bfloat162float(h0)),
             __float2bfloat16(v.y - __bfloat162float(h1)),
             __float2bfloat16(v.z - __bfloat162float(h2)),
             __float2bfloat16(v.w - __bfloat162float(h3)));
}
__device__ __forceinline__ unsigned long long cvt4h(float4 v) {
    union { __half2 h2[2]; unsigned long long u; } t;
    t.h2[0] = __floats2half2_rn(v.x, v.y);
    t.h2[1] = __floats2half2_rn(v.z, v.w);
    return t.u;
}
__device__ __forceinline__ void st8b(__nv_bfloat16* p, unsigned long long v) {
    *(unsigned long long*)p = v;
}
__device__ __forceinline__ void st8h(__half* p, unsigned long long v) {
    *(unsigned long long*)p = v;
}
// barrier across N co-resident CTAs (per-slot counter, prep-zeroed)
template <int N>
__device__ __forceinline__ void grid_barrier(int* ctr) {
    __threadfence();
    __syncthreads();
    if (threadIdx.x == 0) {
        atomicAdd(ctr, 1);
        volatile int* v = ctr;
        while (*v < N) { }
    }
    __syncthreads();
}

// ---------------- one-time prep ----------------
#define N_EMB4 (Tt * Bb * Ee / 4)
#define GAG_Z  (NCH_G * 8192 * 2 / 16)
#define N_CTR  (1 + 3 * Tt + Tt)
__global__ void prep_misc_kernel(const float* __restrict__ b_ih, const float* __restrict__ b_hh,
                                 const float* __restrict__ qz_b, const float* __restrict__ prior_b,
                                 const float* __restrict__ embed_W, const int* __restrict__ captions) {
    int i4 = blockIdx.x * blockDim.x + threadIdx.x;
    if (i4 < N_EMB4) {
        int j = i4 * 4;
        int tb = j >> 9, e = j & 511;
        int t = tb / Bb, b = tb % Bb;
        *(float4*)(g_emb + j) = *(const float4*)(embed_W + (size_t)captions[b * Tt + t] * Ee + e);
        return;
    }
    i4 -= N_EMB4;
    if (i4 < 512) {
        int n = i4 * 4;
        float4 a = *(const float4*)(b_ih + n), b = *(const float4*)(b_hh + n);
        *(float4*)(g_bsum + n) = make_float4(a.x + b.x, a.y + b.y, a.z + b.z, a.w + b.w);
        return;
    }
    i4 -= 512;
    if (i4 < 256) {
        int n = i4 * 4;
        *(float4*)(g_bias_pq + n) = (n < 512) ? *(const float4*)(qz_b + n)
                                              : *(const float4*)(prior_b + n - 512);
        return;
    }
    i4 -= 256;
    if (i4 < Bb * Hh / 4) { *(float4*)(g_c + i4 * 4) = make_float4(0, 0, 0, 0); return; }
    i4 -= Bb * Hh / 4;
    if (i4 < GAG_Z) { *(float4*)((char*)gAg + (size_t)i4 * 16) = make_float4(0, 0, 0, 0); return; }
    i4 -= GAG_Z;
    if (i4 < N_CTR) {
        if (i4 == 0) g_ctrP = 0;
        else if (i4 < 1 + 3 * Tt) { int j = i4 - 1; g_bar3[j / 3][j % 3] = 0; }
        else g_qctr[i4 - 1 - 3 * Tt] = 0;
    }
}
#define PREP_MISC_TOT (N_EMB4 + 512 + 256 + Bb * Hh / 4 + GAG_Z + N_CTR)

// gates weights: N=2048, K order [e(512), z(256), h(512)], fold [hi|lo|hi]
__global__ void prep_wg_kernel(const float* __restrict__ W_ih, const float* __restrict__ W_hh) {
    int idx = blockIdx.x * blockDim.x + threadIdx.x;
    if (idx >= 2048 * 320) return;
    int n = idx / 320, k = (idx - n * 320) * 4;
    float4 v = (k < 768) ? *(const float4*)(W_ih + (size_t)n * 768 + k)
                         : *(const float4*)(W_hh + (size_t)n * 512 + (k - 768));
    unsigned long long hi, lo;
    cvt4(v, hi, lo);
    int tile = n >> 7, row = n & 127;
    __nv_bfloat16* base = gBg + (size_t)tile * NCH_G * 8192;
    st8b(base + ipos(k, row), hi);
    st8b(base + ipos(k + 1280, row), lo);
    st8b(base + ipos(k + 2560, row), hi);
}

// pq weights: N=1024 (qz 0-511, prior 512-1023 padded over e), K order [e, h]
__global__ void prep_wpq_kernel(const float* __restrict__ qz_W, const float* __restrict__ prior_W) {
    int idx = blockIdx.x * blockDim.x + threadIdx.x;
    if (idx >= 1024 * 256) return;
    int n = idx >> 8, k = (idx & 255) << 2;
    float4 v;
    if (n < 512) v = *(const float4*)(qz_W + (size_t)n * 1024 + k);
    else if (k < 512) v = make_float4(0, 0, 0, 0);
    else v = *(const float4*)(prior_W + (size_t)(n - 512) * 512 + (k - 512));
    unsigned long long hi, lo;
    cvt4(v, hi, lo);
    int tile = n >> 7, row = n & 127;
    __nv_bfloat16* base = gBpq + (size_t)tile * NCH_PQ * 8192;
    st8b(base + ipos(k, row), hi);
    st8b(base + ipos(k + 1024, row), lo);
    st8b(base + ipos(k + 2048, row), hi);
}

// qx weights fp16 single: [tile 84][chunk 12][192 x 64]
__global__ void prep_wqx_kernel(const float* __restrict__ qx_W) {
    int idx = blockIdx.x * blockDim.x + threadIdx.x;
    if (idx >= 16128 * 192) return;
    int n = idx / 192, k = (idx - n * 192) * 4;
    float4 v = (n < Vv) ? *(const float4*)(qx_W + (size_t)n * 768 + k)
                        : make_float4(0, 0, 0, 0);
    int tile = n / QROWS, row = n - tile * QROWS;
    __half* base = gBqx + (size_t)tile * (QCH * QROWS * 64);
    st8h(base + (size_t)(k >> 6) * (QROWS * 64) + row * 64 + (k & 63), cvt4h(v));
}

// features A-image (initial step): e-section of gAg (z,h sections pre-zeroed)
__global__ void build_feat_kernel(const float* __restrict__ features) {
    int i4 = blockIdx.x * 512 + threadIdx.x;
    int m = i4 >> 7;
    int e = (i4 & 127) << 2;
    float4 v = *(const float4*)(features + (size_t)m * 512 + e);
    unsigned long long hi, lo;
    cvt4(v, hi, lo);
    st8b(gAg + ipos(e, m), hi);
    st8b(gAg + ipos(e + 1280, m), hi);
    st8b(gAg + ipos(e + 2560, m), lo);
}

// ---------------- folded bf16 GEMM body (pq/gates; 128x128 tiles, 3-stage) ----------------
#define PITCH 144
#define STAGE_B 18432
#define SSZ128 ((128 + 128) * PITCH)
#define SM128 (3 * SSZ128)

__device__ __forceinline__ void load_stage(uint32_t st, const char* srcA, const char* srcB, int tid) {
#pragma unroll
    for (int j = 0; j < 4; j++) {
        int i = tid + j * 256;
        cpasync16(st + (i >> 3) * PITCH + (i & 7) * 16, srcA + i * 16);
    }
#pragma unroll
    for (int j = 0; j < 4; j++) {
        int i = tid + j * 256;
        cpasync16(st + STAGE_B + (i >> 3) * PITCH + (i & 7) * 16, srcB + i * 16);
    }
    asm volatile("cp.async.commit_group;" ::: "memory");
}

__device__ __forceinline__ void gemm_body(
    const __nv_bfloat16* __restrict__ Aimg, const __nv_bfloat16* __restrict__ Bimg,
    int nchunk, float* __restrict__ dst, int ldc, int n0) {
    extern __shared__ __align__(16) char smem[];
    const uint32_t sb = s2u(smem);
    const int tid = threadIdx.x;
    const int wid = tid >> 5;
    const int lane = tid & 31;
    const int warp_m = wid >> 2;
    const int warp_n = wid & 3;

    const char* gA = (const char*)Aimg;
    const char* gB = (const char*)Bimg;

    float acc[4][4][4];
#pragma unroll
    for (int i = 0; i < 4; i++)
#pragma unroll
        for (int j = 0; j < 4; j++)
#pragma unroll
            for (int q = 0; q < 4; q++) acc[i][j][q] = 0.0f;

    const int a_row = lane & 15;
    const int a_coff = (lane >> 4) << 4;
    const int b_row = ((lane >> 4) << 3) | (lane & 7);
    const int b_coff = ((lane >> 3) & 1) << 4;

#pragma unroll
    for (int s = 0; s < 3; s++)
        load_stage(sb + s * SSZ128, gA + (size_t)s * 16384, gB + (size_t)s * 16384, tid);

    int slot = 0;
    for (int c = 0; c < nchunk; c++) {
        asm volatile("cp.async.wait_group 2;" ::: "memory");
        __syncthreads();

        const uint32_t As = sb + slot * SSZ128;
        const uint32_t Bs = As + STAGE_B;
#pragma unroll
        for (int ks = 0; ks < 4; ks++) {
            uint32_t a[4][4];
#pragma unroll
            for (int mi = 0; mi < 4; mi++)
                ldmatrix_x4(a[mi], As + (uint32_t)(warp_m * 64 + mi * 16 + a_row) * PITCH +
                                    ks * 32 + a_coff);
#pragma unroll
            for (int jp = 0; jp < 2; jp++) {
                uint32_t b[4];
                ldmatrix_x4(b, Bs + (uint32_t)(warp_n * 32 + jp * 16 + b_row) * PITCH +
                                ks * 32 + b_coff);
#pragma unroll
                for (int mi = 0; mi < 4; mi++) {
                    mma_bf16(acc[mi][jp * 2 + 0], a[mi], b[0], b[1]);
                    mma_bf16(acc[mi][jp * 2 + 1], a[mi], b[2], b[3]);
                }
            }
        }
        __syncthreads();
        if (c + 3 < nchunk)
            load_stage(sb + slot * SSZ128, gA + (size_t)(c + 3) * 16384,
                       gB + (size_t)(c + 3) * 16384, tid);
        else
            asm volatile("cp.async.commit_group;" ::: "memory");
        slot = (slot == 2) ? 0 : slot + 1;
    }

    const int g = lane >> 2, tq = lane & 3;
#pragma unroll
    for (int mi = 0; mi < 4; mi++) {
        int row = warp_m * 64 + mi * 16 + g;
#pragma unroll
        for (int nj = 0; nj < 4; nj++) {
            int col = n0 + warp_n * 32 + nj * 8 + 2 * tq;
            *(float2*)(dst + (size_t)row * ldc + col) = make_float2(acc[mi][nj][0], acc[mi][nj][1]);
            *(float2*)(dst + (size_t)(row + 8) * ldc + col) = make_float2(acc[mi][nj][2], acc[mi][nj][3]);
        }
    }
}

// ---------------- recurrence tails (device functions, 64-CTA strided) ----------------
__device__ __forceinline__ void z_tail_body(const float* __restrict__ noise,
                                            float* __restrict__ out, int t) {
    __half* aqx = gAqx3[t % 3];
    for (int i4 = blockIdx.x * 256 + threadIdx.x; i4 < Bb * Ll / 4; i4 += REC_CTAS * 256) {
        int m = i4 >> 6;
        int l = (i4 & 63) << 2;
        const int r = m * 1024;
#define SUM8(off) ({ \
        float4 s = *(const float4*)(g_bias_pq + (off)); \
        _Pragma("unroll") \
        for (int sg = 0; sg < 8; sg++) { \
            float4 a = __ldcg((const float4*)(&g_pqp[sg][0] + r + (off))); \
            s.x += a.x; s.y += a.y; s.z += a.z; s.w += a.w; \
        } s; })
        float4 qmu = SUM8(l);
        float4 qsig = SUM8(256 + l);
        float4 pmu = SUM8(512 + l);
        float4 psig = SUM8(768 + l);
#undef SUM8
        size_t o = ((size_t)t * Bb + m) * Ll + l;
        *(float4*)(out + OFF_QMU + o) = qmu;
        *(float4*)(out + OFF_QSIG + o) = qsig;
        *(float4*)(out + OFF_PMU + o) = pmu;
        *(float4*)(out + OFF_PSIG + o) = psig;
        float4 nz = *(const float4*)(noise + ((size_t)m * Tt + t) * Ll + l);
        float4 z = make_float4(nz.x * qsig.x + qmu.x, nz.y * qsig.y + qmu.y,
                               nz.z * qsig.z + qmu.z, nz.w * qsig.w + qmu.w);
        unsigned long long hi, lo;
        cvt4(z, hi, lo);
        int kg = 512 + l;
        st8b(gAg + ipos(kg, m), hi);
        st8b(gAg + ipos(kg + 1280, m), hi);
        st8b(gAg + ipos(kg + 2560, m), lo);
        st8h(aqx + qpos16(l, m), cvt4h(z));
    }
}

__device__ __forceinline__ void lstm_tail_body(int t_next) {
    __half* aqx = gAqx3[t_next % 3];
    for (int i4 = blockIdx.x * 256 + threadIdx.x; i4 < Bb * Hh / 4; i4 += REC_CTAS * 256) {
        int b = i4 >> 7;
        int n = (i4 & 127) << 2;
        const int r = b * 2048;
#define GSUM(off) ({ \
        float4 s = *(const float4*)(g_bsum + (off)); \
        _Pragma("unroll") \
        for (int sg = 0; sg < 4; sg++) { \
            float4 a = __ldcg((const float4*)(&g_gp[sg][0] + r + (off))); \
            s.x += a.x; s.y += a.y; s.z += a.z; s.w += a.w; \
        } s; })
        float4 gi = GSUM(n);
        float4 gf = GSUM(512 + n);
        float4 gg = GSUM(1024 + n);
        float4 go = GSUM(1536 + n);
#undef GSUM
        float4 co = *(const float4*)(g_c + b * 512 + n);
        float4 cn, h;
        cn.x = sigf(gf.x) * co.x + sigf(gi.x) * tanhf(gg.x);
        cn.y = sigf(gf.y) * co.y + sigf(gi.y) * tanhf(gg.y);
        cn.z = sigf(gf.z) * co.z + sigf(gi.z) * tanhf(gg.z);
        cn.w = sigf(gf.w) * co.w + sigf(gi.w) * tanhf(gg.w);
        h.x = sigf(go.x) * tanhf(cn.x);
        h.y = sigf(go.y) * tanhf(cn.y);
        h.z = sigf(go.z) * tanhf(cn.z);
        h.w = sigf(go.w) * tanhf(cn.w);
        *(float4*)(g_c + b * 512 + n) = cn;
        unsigned long long hi, lo;
        cvt4(h, hi, lo);
        int k = 512 + n;
        st8b(gApq + ipos(k, b), hi);
        st8b(gApq + ipos(k + 1024, b), hi);
        st8b(gApq + ipos(k + 2048, b), lo);
        int kg = 768 + n;
        st8b(gAg + ipos(kg, b), hi);
        st8b(gAg + ipos(kg + 1280, b), hi);
        st8b(gAg + ipos(kg + 2560, b), lo);
        st8h(aqx + qpos16(256 + n, b), cvt4h(h));
    }
    if (t_next < Tt) {
        const float* src = g_emb + (((size_t)t_next * Bb) << 9);
        for (int i4 = blockIdx.x * 256 + threadIdx.x; i4 < Bb * Ee / 4; i4 += REC_CTAS * 256) {
            int m = i4 >> 7;
            int e = (i4 & 127) << 2;
            float4 v = *(const float4*)(src + ((size_t)m << 9) + e);
            unsigned long long hi, lo;
            cvt4(v, hi, lo);
            st8b(gApq + ipos(e, m), hi);
            st8b(gApq + ipos(e + 1024, m), hi);
            st8b(gApq + ipos(e + 2048, m), lo);
            st8b(gAg + ipos(e, m), hi);
            st8b(gAg + ipos(e + 1280, m), hi);
            st8b(gAg + ipos(e + 2560, m), lo);
        }
    }
}

// ---------------- prologue: gates GEMM + LSTM tail (t=0 images) ----------------
__global__ void __launch_bounds__(256) prolog_kernel() {
    int seg = blockIdx.x >> 4, tile = blockIdx.x & 15;
    gemm_body(gAg + (size_t)seg * 15 * 8192,
              gBg + ((size_t)tile * NCH_G + seg * 15) * 8192,
              15, g_gp[seg], 2048, tile << 7);
    grid_barrier<REC_CTAS>(&g_ctrP);
    lstm_tail_body(0);
}

// ---------------- fused per-step recurrence kernel (64 CTAs) ----------------
__global__ void __launch_bounds__(256) rec_step_kernel(const float* __restrict__ noise,
                                                       float* __restrict__ out, int t) {
    {
        int seg = blockIdx.x >> 3, tile = blockIdx.x & 7;
        gemm_body(gApq + (size_t)seg * 6 * 8192,
                  gBpq + ((size_t)tile * NCH_PQ + seg * 6) * 8192,
                  6, g_pqp[seg], 1024, tile << 7);
    }
    grid_barrier<REC_CTAS>(&g_bar3[t][0]);
    z_tail_body(noise, out, t);
    grid_barrier<REC_CTAS>(&g_bar3[t][1]);
    {
        int seg = blockIdx.x >> 4, tile = blockIdx.x & 15;
        gemm_body(gAg + (size_t)seg * 15 * 8192,
                  gBg + ((size_t)tile * NCH_G + seg * 15) * 8192,
                  15, g_gp[seg], 2048, tile << 7);
    }
    grid_barrier<REC_CTAS>(&g_bar3[t][2]);
    lstm_tail_body(t + 1);
}

// ---------------- fused qx GEMM + log-softmax (84 CTAs, fp16, 3-stage) ----------------
#define STAGE_A16 (128 * PITCH)             // 18432
#define QSTG ((128 + 192) * PITCH)          // 46080
#define SMQX (3 * QSTG)                     // 138240

__device__ __forceinline__ void load_stage_qx(uint32_t st, const char* srcA, const char* srcB,
                                              int tid) {
#pragma unroll
    for (int j = 0; j < 4; j++) {          // A: 16KB
        int i = tid + j * 256;
        cpasync16(st + (i >> 3) * PITCH + (i & 7) * 16, srcA + i * 16);
    }
#pragma unroll
    for (int j = 0; j < 6; j++) {          // B: 24KB
        int i = tid + j * 256;
        cpasync16(st + STAGE_A16 + (i >> 3) * PITCH + (i & 7) * 16, srcB + i * 16);
    }
    asm volatile("cp.async.commit_group;" ::: "memory");
}

// log-softmax over one row (256 threads)
__device__ void softmax_row(float* __restrict__ x) {
    __shared__ float sred[8];
    __shared__ float sval;
    const int tid = threadIdx.x;
    float m = -3.4e38f;
    for (int i = tid; i < Vv; i += 256) m = fmaxf(m, x[i]);
#pragma unroll
    for (int o = 16; o; o >>= 1) m = fmaxf(m, __shfl_xor_sync(0xffffffffu, m, o));
    if ((tid & 31) == 0) sred[tid >> 5] = m;
    __syncthreads();
    if (tid < 32) {
        float v = (tid < 8) ? sred[tid] : -3.4e38f;
#pragma unroll
        for (int o = 4; o; o >>= 1) v = fmaxf(v, __shfl_xor_sync(0xffffffffu, v, o));
        if (tid == 0) sval = v;
    }
    __syncthreads();
    m = sval;
    float s = 0.0f;
    for (int i = tid; i < Vv; i += 256) s += expf(x[i] - m);
#pragma unroll
    for (int o = 16; o; o >>= 1) s += __shfl_xor_sync(0xffffffffu, s, o);
    __syncthreads();
    if ((tid & 31) == 0) sred[tid >> 5] = s;
    __syncthreads();
    if (tid < 32) {
        float v = (tid < 8) ? sred[tid] : 0.0f;
#pragma unroll
        for (int o = 4; o; o >>= 1) v += __shfl_xor_sync(0xffffffffu, v, o);
        if (tid == 0) sval = m + logf(v);
    }
    __syncthreads();
    float lz = sval;
    for (int i = tid; i < Vv; i += 256) x[i] -= lz;
    __syncthreads();
}

__global__ void __launch_bounds__(256) qxsm_kernel(const float* __restrict__ qx_b,
                                                   float* __restrict__ dst, int t, int par) {
    extern __shared__ __align__(16) char smem[];
    const uint32_t sb = s2u(smem);
    const int tid = threadIdx.x;
    const int wid = tid >> 5;
    const int lane = tid & 31;
    const int warp_m = wid >> 2;
    const int warp_n = wid & 3;
    const int n0 = blockIdx.x * QROWS;

    const char* gA = (const char*)gAqx3[par];
    const char* gB = (const char*)(gBqx + (size_t)blockIdx.x * (QCH * QROWS * 64));

    float acc[4][6][4];
#pragma unroll
    for (int i = 0; i < 4; i++)
#pragma unroll
        for (int j = 0; j < 6; j++)
#pragma unroll
            for (int q = 0; q < 4; q++) acc[i][j][q] = 0.0f;

    const int a_row = lane & 15;
    const int a_coff = (lane >> 4) << 4;
    const int b_row = ((lane >> 4) << 3) | (lane & 7);
    const int b_coff = ((lane >> 3) & 1) << 4;

#pragma unroll
    for (int s = 0; s < 3; s++)
        load_stage_qx(sb + s * QSTG, gA + (size_t)s * 16384, gB + (size_t)s * 24576, tid);

    int slot = 0;
    for (int c = 0; c < QCH; c++) {
        asm volatile("cp.async.wait_group 2;" ::: "memory");
        __syncthreads();

        const uint32_t As = sb + slot * QSTG;
        const uint32_t Bs = As + STAGE_A16;
#pragma unroll
        for (int ks = 0; ks < 4; ks++) {
            uint32_t a[4][4];
#pragma unroll
            for (int mi = 0; mi < 4; mi++)
                ldmatrix_x4(a[mi], As + (uint32_t)(warp_m * 64 + mi * 16 + a_row) * PITCH +
                                    ks * 32 + a_coff);
#pragma unroll
            for (int jp = 0; jp < 3; jp++) {
                uint32_t b[4];
                ldmatrix_x4(b, Bs + (uint32_t)(warp_n * 48 + jp * 16 + b_row) * PITCH +
                                ks * 32 + b_coff);
#pragma unroll
                for (int mi = 0; mi < 4; mi++) {
                    mma_f16(acc[mi][jp * 2 + 0], a[mi], b[0], b[1]);
                    mma_f16(acc[mi][jp * 2 + 1], a[mi], b[2], b[3]);
                }
            }
        }
        __syncthreads();
        if (c + 3 < QCH)
            load_stage_qx(sb + slot * QSTG, gA + (size_t)(c + 3) * 16384,
                          gB + (size_t)(c + 3) * 24576, tid);
        else
            asm volatile("cp.async.commit_group;" ::: "memory");
        slot = (slot == 2) ? 0 : slot + 1;
    }

    const int g = lane >> 2, tq = lane & 3;
#pragma unroll
    for (int mi = 0; mi < 4; mi++) {
        int row = warp_m * 64 + mi * 16 + g;
#pragma unroll
        for (int nj = 0; nj < 6; nj++) {
            int col = n0 + warp_n * 48 + nj * 8 + 2 * tq;
            if (col >= Vv) continue;
            float b0 = qx_b[col], b1 = qx_b[col + 1];
            *(float2*)(dst + (size_t)row * Vv + col) =
                make_float2(acc[mi][nj][0] + b0, acc[mi][nj][1] + b1);
            *(float2*)(dst + (size_t)(row + 8) * Vv + col) =
                make_float2(acc[mi][nj][2] + b0, acc[mi][nj][3] + b1);
        }
    }

    // all-84 barrier, then log-softmax (CTA r handles rows r and r+84)
    grid_barrier<QX_CTAS>(&g_qctr[t]);
    softmax_row(dst + (size_t)blockIdx.x * Vv);
    if (blockIdx.x + QX_CTAS < Bb)
        softmax_row(dst + (size_t)(blockIdx.x + QX_CTAS) * Vv);
}

extern "C" void kernel_launch(void* const* d_in, const int* in_sizes, int n_in,
                              void* d_out, int out_size) {
    const float* features = (const float*)d_in[0];
    const int* captions = (const int*)d_in[1];
    const float* noise   = (const float*)d_in[3];
    const float* embed_W = (const float*)d_in[4];
    const float* W_ih    = (const float*)d_in[5];
    const float* W_hh    = (const float*)d_in[6];
    const float* b_ih    = (const float*)d_in[7];
    const float* b_hh    = (const float*)d_in[8];
    const float* qz_W    = (const float*)d_in[9];
    const float* qz_b    = (const float*)d_in[10];
    const float* prior_W = (const float*)d_in[11];
    const float* prior_b = (const float*)d_in[12];
    const float* qx_W    = (const float*)d_in[13];
    const float* qx_b    = (const float*)d_in[14];
    float* out = (float*)d_out;

    static cudaStream_t s1 = nullptr, s2 = nullptr;
    static cudaEvent_t evF = nullptr, evZ = nullptr, evQ[3] = {nullptr, nullptr, nullptr};
    static cudaEvent_t evW = nullptr, evJ1 = nullptr;
    if (s1 == nullptr) {
        cudaStreamCreateWithFlags(&s1, cudaStreamNonBlocking);
        cudaStreamCreateWithFlags(&s2, cudaStreamNonBlocking);
        cudaEventCreateWithFlags(&evF, cudaEventDisableTiming);
        cudaEventCreateWithFlags(&evZ, cudaEventDisableTiming);
        for (int i = 0; i < 3; i++) cudaEventCreateWithFlags(&evQ[i], cudaEventDisableTiming);
        cudaEventCreateWithFlags(&evW, cudaEventDisableTiming);
        cudaEventCreateWithFlags(&evJ1, cudaEventDisableTiming);
    }

    cudaFuncSetAttribute(prolog_kernel, cudaFuncAttributeMaxDynamicSharedMemorySize, SM128);
    cudaFuncSetAttribute(rec_step_kernel, cudaFuncAttributeMaxDynamicSharedMemorySize, SM128);
    cudaFuncSetAttribute(qxsm_kernel, cudaFuncAttributeMaxDynamicSharedMemorySize, SMQX);

    // one-time prep — fork side streams from the capture stream via an event
    prep_misc_kernel<<<(PREP_MISC_TOT + 255) / 256, 256>>>(b_ih, b_hh, qz_b, prior_b,
                                                           embed_W, captions);
    cudaEventRecord(evF, 0);
    cudaStreamWaitEvent(s1, evF, 0);
    cudaStreamWaitEvent(s2, evF, 0);
    prep_wqx_kernel<<<(16128 * 192 + 255) / 256, 256, 0, s1>>>(qx_W);   // ordered before qxsm on s1
    prep_wg_kernel<<<(2048 * 320 + 255) / 256, 256, 0, s2>>>(W_ih, W_hh);
    prep_wpq_kernel<<<(1024 * 256 + 255) / 256, 256>>>(qz_W, prior_W);
    cudaEventRecord(evW, s2);
    cudaStreamWaitEvent(0, evW, 0);   // gBg ready before prolog on stream 0

    // initial LSTM step: features through the gates tc path (z,h image sections are zero)
    build_feat_kernel<<<32, 512>>>(features);
    prolog_kernel<<<REC_CTAS, 256, SM128>>>();

    for (int t = 0; t < Tt; t++) {
        // rec_step(t)'s lstm tail writes qx A-buffer (t+1)%3, last read by qxsm(t-2)
        if (t >= 2) cudaStreamWaitEvent(0, evQ[(t + 1) % 3], 0);
        rec_step_kernel<<<REC_CTAS, 256, SM128>>>(noise, out, t);
        cudaEventRecord(evZ, 0);
        cudaStreamWaitEvent(s1, evZ, 0);
        float* qx_dst = out + OFF_QX + (size_t)t * Bb * Vv;
        qxsm_kernel<<<QX_CTAS, 256, SMQX, s1>>>(qx_b, qx_dst, t, t % 3);
        cudaEventRecord(evQ[t % 3], s1);
    }

    cudaEventRecord(evJ1, s1);
    cudaStreamWaitEvent(0, evJ1, 0);
}

// round 13
// speedup vs baseline: 1.7533x; 1.0604x over previous
#include <cuda_runtime.h>
#include <cuda_bf16.h>
#include <cuda_fp16.h>
#include <math.h>
#include <stdint.h>

// Problem constants
#define Bb 128
#define Tt 32
#define Ee 512
#define Hh 512
#define Ll 256
#define Vv 16000

#define NCH_G  60      // gates: K2=3840 (folded bf16)
#define NCH_PQ 48      // pq: K2=3072 (folded bf16)
#define QROWS  192
#define QCH    12      // qx chunks of 64 over K=768 (fp16 single)
#define REC_CTAS 64
#define QX_CTAS  84

// Output layout: p_mus, p_sigmas, q_mus, q_sigmas, q_xs
#define OFF_PMU  ((size_t)0)
#define OFF_PSIG ((size_t)Tt * Bb * Ll)
#define OFF_QMU  ((size_t)2 * Tt * Bb * Ll)
#define OFF_QSIG ((size_t)3 * Tt * Bb * Ll)
#define OFF_QX   ((size_t)4 * Tt * Bb * Ll)

// ---------------- device scratch ----------------
__device__ float g_emb[Tt * Bb * Ee];
__device__ float g_bsum[4 * Hh];
__device__ float g_bias_pq[1024];
__device__ float g_c[Bb * Hh];
__device__ float g_pqp[8][Bb * 1024];    // pq split-K partials (8 segs)
__device__ float g_gp[4][Bb * 2048];     // gates split-K partials (4 segs)
__device__ int g_ctrP;                   // prologue barrier
__device__ int g_bar2[Tt][2];            // rec_step internal barriers
__device__ int g_flagZ[Tt];              // z-images ready (==64)
__device__ int g_flagQ[Tt];              // qx GEMM done (==84)

// Weight images (once)
__device__ __align__(16) __nv_bfloat16 gBg[(size_t)16 * NCH_G * 8192];
__device__ __align__(16) __nv_bfloat16 gBpq[(size_t)8 * NCH_PQ * 8192];
__device__ __align__(16) __half gBqx[(size_t)QX_CTAS * QCH * QROWS * 64];   // fp16 single
// A images: pq/gates folded bf16 single; qx fp16 triple-buffered
__device__ __align__(16) __nv_bfloat16 gAg[NCH_G * 8192];
__device__ __align__(16) __nv_bfloat16 gApq[NCH_PQ * 8192];
__device__ __align__(16) __half gAqx3[3][QCH * 8192];

__device__ __forceinline__ float sigf(float x) { return 1.0f / (1.0f + expf(-x)); }

__device__ __forceinline__ uint32_t s2u(const void* p) {
    uint32_t a;
    asm("{ .reg .u64 t; cvta.to.shared.u64 t, %1; cvt.u32.u64 %0, t; }" : "=r"(a) : "l"(p));
    return a;
}
__device__ __forceinline__ void cpasync16(uint32_t dst, const void* src) {
    asm volatile("cp.async.cg.shared.global [%0], [%1], 16;"
                 :: "r"(dst), "l"(__cvta_generic_to_global(src)) : "memory");
}
__device__ __forceinline__ void ldmatrix_x4(uint32_t* r, uint32_t addr) {
    asm volatile("ldmatrix.sync.aligned.m8n8.x4.shared.b16 {%0,%1,%2,%3}, [%4];"
                 : "=r"(r[0]), "=r"(r[1]), "=r"(r[2]), "=r"(r[3]) : "r"(addr));
}
__device__ __forceinline__ void mma_bf16(float* c, const uint32_t* a, uint32_t b0, uint32_t b1) {
    asm volatile(
        "mma.sync.aligned.m16n8k16.row.col.f32.bf16.bf16.f32 "
        "{%0,%1,%2,%3}, {%4,%5,%6,%7}, {%8,%9}, {%0,%1,%2,%3};"
        : "+f"(c[0]), "+f"(c[1]), "+f"(c[2]), "+f"(c[3])
        : "r"(a[0]), "r"(a[1]), "r"(a[2]), "r"(a[3]), "r"(b0), "r"(b1));
}
__device__ __forceinline__ void mma_f16(float* c, const uint32_t* a, uint32_t b0, uint32_t b1) {
    asm volatile(
        "mma.sync.aligned.m16n8k16.row.col.f32.f16.f16.f32 "
        "{%0,%1,%2,%3}, {%4,%5,%6,%7}, {%8,%9}, {%0,%1,%2,%3};"
        : "+f"(c[0]), "+f"(c[1]), "+f"(c[2]), "+f"(c[3])
        : "r"(a[0]), "r"(a[1]), "r"(a[2]), "r"(a[3]), "r"(b0), "r"(b1));
}
__device__ __forceinline__ size_t ipos(int k2, int m) {      // bf16 folded images
    return (((size_t)(k2 >> 6) * 128 + m) << 6) + (k2 & 63);
}
__device__ __forceinline__ size_t qpos16(int k, int m) {     // fp16 qx A image
    return (size_t)(k >> 6) * 8192 + m * 64 + (k & 63);
}
__device__ __forceinline__ unsigned long long pk4(__nv_bfloat16 a, __nv_bfloat16 b,
                                                  __nv_bfloat16 c, __nv_bfloat16 d) {
    union { __nv_bfloat16 h[4]; unsigned long long u; } t;
    t.h[0] = a; t.h[1] = b; t.h[2] = c; t.h[3] = d;
    return t.u;
}
__device__ __forceinline__ void cvt4(float4 v, unsigned long long& hi, unsigned long long& lo) {
    __nv_bfloat16 h0 = __float2bfloat16(v.x), h1 = __float2bfloat16(v.y);
    __nv_bfloat16 h2 = __float2bfloat16(v.z), h3 = __float2bfloat16(v.w);
    hi = pk4(h0, h1, h2, h3);
    lo = pk4(__float2bfloat16(v.x - __bfloat162float(h0)),
             __float2bfloat16(v.y - __bfloat162float(h1)),
             __float2bfloat16(v.z - __bfloat162float(h2)),
             __float2bfloat16(v.w - __bfloat162float(h3)));
}
__device__ __forceinline__ unsigned long long cvt4h(float4 v) {
    union { __half2 h2[2]; unsigned long long u; } t;
    t.h2[0] = __floats2half2_rn(v.x, v.y);
    t.h2[1] = __floats2half2_rn(v.z, v.w);
    return t.u;
}
__device__ __forceinline__ void st8b(__nv_bfloat16* p, unsigned long long v) {
    *(unsigned long long*)p = v;
}
__device__ __forceinline__ void st8h(__half* p, unsigned long long v) {
    *(unsigned long long*)p = v;
}
// barrier across N co-resident CTAs (per-slot counter, prep-zeroed)
template <int N>
__device__ __forceinline__ void grid_barrier(int* ctr) {
    __threadfence();
    __syncthreads();
    if (threadIdx.x == 0) {
        atomicAdd(ctr, 1);
        volatile int* v = ctr;
        while (*v < N) { }
    }
    __syncthreads();
}
// signal + wait (fence, add 1, wait for N) — doubles as barrier when all N add
template <int N>
__device__ __forceinline__ void signal_wait(int* ctr) {
    __threadfence();
    __syncthreads();
    if (threadIdx.x == 0) {
        atomicAdd(ctr, 1);
        volatile int* v = ctr;
        while (*v < N) { }
    }
    __syncthreads();
}
__device__ __forceinline__ void wait_count(int* ctr, int target) {
    if (threadIdx.x == 0) {
        volatile int* v = ctr;
        while (*v < target) { }
    }
    __syncthreads();
}

// ---------------- one-time prep ----------------
#define N_EMB4 (Tt * Bb * Ee / 4)
#define GAG_Z  (NCH_G * 8192 * 2 / 16)
#define N_CTR  (1 + 2 * Tt + Tt + Tt)
__global__ void prep_misc_kernel(const float* __restrict__ b_ih, const float* __restrict__ b_hh,
                                 const float* __restrict__ qz_b, const float* __restrict__ prior_b,
                                 const float* __restrict__ embed_W, const int* __restrict__ captions) {
    int i4 = blockIdx.x * blockDim.x + threadIdx.x;
    if (i4 < N_EMB4) {
        int j = i4 * 4;
        int tb = j >> 9, e = j & 511;
        int t = tb / Bb, b = tb % Bb;
        *(float4*)(g_emb + j) = *(const float4*)(embed_W + (size_t)captions[b * Tt + t] * Ee + e);
        return;
    }
    i4 -= N_EMB4;
    if (i4 < 512) {
        int n = i4 * 4;
        float4 a = *(const float4*)(b_ih + n), b = *(const float4*)(b_hh + n);
        *(float4*)(g_bsum + n) = make_float4(a.x + b.x, a.y + b.y, a.z + b.z, a.w + b.w);
        return;
    }
    i4 -= 512;
    if (i4 < 256) {
        int n = i4 * 4;
        *(float4*)(g_bias_pq + n) = (n < 512) ? *(const float4*)(qz_b + n)
                                              : *(const float4*)(prior_b + n - 512);
        return;
    }
    i4 -= 256;
    if (i4 < Bb * Hh / 4) { *(float4*)(g_c + i4 * 4) = make_float4(0, 0, 0, 0); return; }
    i4 -= Bb * Hh / 4;
    if (i4 < GAG_Z) { *(float4*)((char*)gAg + (size_t)i4 * 16) = make_float4(0, 0, 0, 0); return; }
    i4 -= GAG_Z;
    if (i4 < N_CTR) {
        if (i4 == 0) g_ctrP = 0;
        else if (i4 < 1 + 2 * Tt) { int j = i4 - 1; g_bar2[j >> 1][j & 1] = 0; }
        else if (i4 < 1 + 2 * Tt + Tt) g_flagZ[i4 - 1 - 2 * Tt] = 0;
        else g_flagQ[i4 - 1 - 3 * Tt] = 0;
    }
}
#define PREP_MISC_TOT (N_EMB4 + 512 + 256 + Bb * Hh / 4 + GAG_Z + N_CTR)

// gates weights: N=2048, K order [e(512), z(256), h(512)], fold [hi|lo|hi]
__global__ void prep_wg_kernel(const float* __restrict__ W_ih, const float* __restrict__ W_hh) {
    int idx = blockIdx.x * blockDim.x + threadIdx.x;
    if (idx >= 2048 * 320) return;
    int n = idx / 320, k = (idx - n * 320) * 4;
    float4 v = (k < 768) ? *(const float4*)(W_ih + (size_t)n * 768 + k)
                         : *(const float4*)(W_hh + (size_t)n * 512 + (k - 768));
    unsigned long long hi, lo;
    cvt4(v, hi, lo);
    int tile = n >> 7, row = n & 127;
    __nv_bfloat16* base = gBg + (size_t)tile * NCH_G * 8192;
    st8b(base + ipos(k, row), hi);
    st8b(base + ipos(k + 1280, row), lo);
    st8b(base + ipos(k + 2560, row), hi);
}

// pq weights: N=1024 (qz 0-511, prior 512-1023 padded over e), K order [e, h]
__global__ void prep_wpq_kernel(const float* __restrict__ qz_W, const float* __restrict__ prior_W) {
    int idx = blockIdx.x * blockDim.x + threadIdx.x;
    if (idx >= 1024 * 256) return;
    int n = idx >> 8, k = (idx & 255) << 2;
    float4 v;
    if (n < 512) v = *(const float4*)(qz_W + (size_t)n * 1024 + k);
    else if (k < 512) v = make_float4(0, 0, 0, 0);
    else v = *(const float4*)(prior_W + (size_t)(n - 512) * 512 + (k - 512));
    unsigned long long hi, lo;
    cvt4(v, hi, lo);
    int tile = n >> 7, row = n & 127;
    __nv_bfloat16* base = gBpq + (size_t)tile * NCH_PQ * 8192;
    st8b(base + ipos(k, row), hi);
    st8b(base + ipos(k + 1024, row), lo);
    st8b(base + ipos(k + 2048, row), hi);
}

// qx weights fp16 single: [tile 84][chunk 12][192 x 64]
__global__ void prep_wqx_kernel(const float* __restrict__ qx_W) {
    int idx = blockIdx.x * blockDim.x + threadIdx.x;
    if (idx >= 16128 * 192) return;
    int n = idx / 192, k = (idx - n * 192) * 4;
    float4 v = (n < Vv) ? *(const float4*)(qx_W + (size_t)n * 768 + k)
                        : make_float4(0, 0, 0, 0);
    int tile = n / QROWS, row = n - tile * QROWS;
    __half* base = gBqx + (size_t)tile * (QCH * QROWS * 64);
    st8h(base + (size_t)(k >> 6) * (QROWS * 64) + row * 64 + (k & 63), cvt4h(v));
}

// features A-image (initial step): e-section of gAg (z,h sections pre-zeroed)
__global__ void build_feat_kernel(const float* __restrict__ features) {
    int i4 = blockIdx.x * 512 + threadIdx.x;
    int m = i4 >> 7;
    int e = (i4 & 127) << 2;
    float4 v = *(const float4*)(features + (size_t)m * 512 + e);
    unsigned long long hi, lo;
    cvt4(v, hi, lo);
    st8b(gAg + ipos(e, m), hi);
    st8b(gAg + ipos(e + 1280, m), hi);
    st8b(gAg + ipos(e + 2560, m), lo);
}

// ---------------- folded bf16 GEMM body (pq/gates; 128x128 tiles, 3-stage) ----------------
#define PITCH 144
#define STAGE_B 18432
#define SSZ128 ((128 + 128) * PITCH)
#define SM128 (3 * SSZ128)

__device__ __forceinline__ void load_stage(uint32_t st, const char* srcA, const char* srcB, int tid) {
#pragma unroll
    for (int j = 0; j < 4; j++) {
        int i = tid + j * 256;
        cpasync16(st + (i >> 3) * PITCH + (i & 7) * 16, srcA + i * 16);
    }
#pragma unroll
    for (int j = 0; j < 4; j++) {
        int i = tid + j * 256;
        cpasync16(st + STAGE_B + (i >> 3) * PITCH + (i & 7) * 16, srcB + i * 16);
    }
    asm volatile("cp.async.commit_group;" ::: "memory");
}

__device__ __forceinline__ void gemm_body(
    const __nv_bfloat16* __restrict__ Aimg, const __nv_bfloat16* __restrict__ Bimg,
    int nchunk, float* __restrict__ dst, int ldc, int n0) {
    extern __shared__ __align__(16) char smem[];
    const uint32_t sb = s2u(smem);
    const int tid = threadIdx.x;
    const int wid = tid >> 5;
    const int lane = tid & 31;
    const int warp_m = wid >> 2;
    const int warp_n = wid & 3;

    const char* gA = (const char*)Aimg;
    const char* gB = (const char*)Bimg;

    float acc[4][4][4];
#pragma unroll
    for (int i = 0; i < 4; i++)
#pragma unroll
        for (int j = 0; j < 4; j++)
#pragma unroll
            for (int q = 0; q < 4; q++) acc[i][j][q] = 0.0f;

    const int a_row = lane & 15;
    const int a_coff = (lane >> 4) << 4;
    const int b_row = ((lane >> 4) << 3) | (lane & 7);
    const int b_coff = ((lane >> 3) & 1) << 4;

#pragma unroll
    for (int s = 0; s < 3; s++)
        load_stage(sb + s * SSZ128, gA + (size_t)s * 16384, gB + (size_t)s * 16384, tid);

    int slot = 0;
    for (int c = 0; c < nchunk; c++) {
        asm volatile("cp.async.wait_group 2;" ::: "memory");
        __syncthreads();

        const uint32_t As = sb + slot * SSZ128;
        const uint32_t Bs = As + STAGE_B;
#pragma unroll
        for (int ks = 0; ks < 4; ks++) {
            uint32_t a[4][4];
#pragma unroll
            for (int mi = 0; mi < 4; mi++)
                ldmatrix_x4(a[mi], As + (uint32_t)(warp_m * 64 + mi * 16 + a_row) * PITCH +
                                    ks * 32 + a_coff);
#pragma unroll
            for (int jp = 0; jp < 2; jp++) {
                uint32_t b[4];
                ldmatrix_x4(b, Bs + (uint32_t)(warp_n * 32 + jp * 16 + b_row) * PITCH +
                                ks * 32 + b_coff);
#pragma unroll
                for (int mi = 0; mi < 4; mi++) {
                    mma_bf16(acc[mi][jp * 2 + 0], a[mi], b[0], b[1]);
                    mma_bf16(acc[mi][jp * 2 + 1], a[mi], b[2], b[3]);
                }
            }
        }
        __syncthreads();
        if (c + 3 < nchunk)
            load_stage(sb + slot * SSZ128, gA + (size_t)(c + 3) * 16384,
                       gB + (size_t)(c + 3) * 16384, tid);
        else
            asm volatile("cp.async.commit_group;" ::: "memory");
        slot = (slot == 2) ? 0 : slot + 1;
    }

    const int g = lane >> 2, tq = lane & 3;
#pragma unroll
    for (int mi = 0; mi < 4; mi++) {
        int row = warp_m * 64 + mi * 16 + g;
#pragma unroll
        for (int nj = 0; nj < 4; nj++) {
            int col = n0 + warp_n * 32 + nj * 8 + 2 * tq;
            *(float2*)(dst + (size_t)row * ldc + col) = make_float2(acc[mi][nj][0], acc[mi][nj][1]);
            *(float2*)(dst + (size_t)(row + 8) * ldc + col) = make_float2(acc[mi][nj][2], acc[mi][nj][3]);
        }
    }
}

// ---------------- recurrence tails (device functions, 64-CTA strided) ----------------
__device__ __forceinline__ void z_tail_body(const float* __restrict__ noise,
                                            float* __restrict__ out, int t) {
    __half* aqx = gAqx3[t % 3];
    for (int i4 = blockIdx.x * 256 + threadIdx.x; i4 < Bb * Ll / 4; i4 += REC_CTAS * 256) {
        int m = i4 >> 6;
        int l = (i4 & 63) << 2;
        const int r = m * 1024;
#define SUM8(off) ({ \
        float4 s = *(const float4*)(g_bias_pq + (off)); \
        _Pragma("unroll") \
        for (int sg = 0; sg < 8; sg++) { \
            float4 a = __ldcg((const float4*)(&g_pqp[sg][0] + r + (off))); \
            s.x += a.x; s.y += a.y; s.z += a.z; s.w += a.w; \
        } s; })
        float4 qmu = SUM8(l);
        float4 qsig = SUM8(256 + l);
        float4 pmu = SUM8(512 + l);
        float4 psig = SUM8(768 + l);
#undef SUM8
        size_t o = ((size_t)t * Bb + m) * Ll + l;
        *(float4*)(out + OFF_QMU + o) = qmu;
        *(float4*)(out + OFF_QSIG + o) = qsig;
        *(float4*)(out + OFF_PMU + o) = pmu;
        *(float4*)(out + OFF_PSIG + o) = psig;
        float4 nz = *(const float4*)(noise + ((size_t)m * Tt + t) * Ll + l);
        float4 z = make_float4(nz.x * qsig.x + qmu.x, nz.y * qsig.y + qmu.y,
                               nz.z * qsig.z + qmu.z, nz.w * qsig.w + qmu.w);
        unsigned long long hi, lo;
        cvt4(z, hi, lo);
        int kg = 512 + l;
        st8b(gAg + ipos(kg, m), hi);
        st8b(gAg + ipos(kg + 1280, m), hi);
        st8b(gAg + ipos(kg + 2560, m), lo);
        st8h(aqx + qpos16(l, m), cvt4h(z));
    }
}

__device__ __forceinline__ void lstm_tail_body(int t_next) {
    __half* aqx = gAqx3[t_next % 3];
    for (int i4 = blockIdx.x * 256 + threadIdx.x; i4 < Bb * Hh / 4; i4 += REC_CTAS * 256) {
        int b = i4 >> 7;
        int n = (i4 & 127) << 2;
        const int r = b * 2048;
#define GSUM(off) ({ \
        float4 s = *(const float4*)(g_bsum + (off)); \
        _Pragma("unroll") \
        for (int sg = 0; sg < 4; sg++) { \
            float4 a = __ldcg((const float4*)(&g_gp[sg][0] + r + (off))); \
            s.x += a.x; s.y += a.y; s.z += a.z; s.w += a.w; \
        } s; })
        float4 gi = GSUM(n);
        float4 gf = GSUM(512 + n);
        float4 gg = GSUM(1024 + n);
        float4 go = GSUM(1536 + n);
#undef GSUM
        float4 co = *(const float4*)(g_c + b * 512 + n);
        float4 cn, h;
        cn.x = sigf(gf.x) * co.x + sigf(gi.x) * tanhf(gg.x);
        cn.y = sigf(gf.y) * co.y + sigf(gi.y) * tanhf(gg.y);
        cn.z = sigf(gf.z) * co.z + sigf(gi.z) * tanhf(gg.z);
        cn.w = sigf(gf.w) * co.w + sigf(gi.w) * tanhf(gg.w);
        h.x = sigf(go.x) * tanhf(cn.x);
        h.y = sigf(go.y) * tanhf(cn.y);
        h.z = sigf(go.z) * tanhf(cn.z);
        h.w = sigf(go.w) * tanhf(cn.w);
        *(float4*)(g_c + b * 512 + n) = cn;
        unsigned long long hi, lo;
        cvt4(h, hi, lo);
        int k = 512 + n;
        st8b(gApq + ipos(k, b), hi);
        st8b(gApq + ipos(k + 1024, b), hi);
        st8b(gApq + ipos(k + 2048, b), lo);
        int kg = 768 + n;
        st8b(gAg + ipos(kg, b), hi);
        st8b(gAg + ipos(kg + 1280, b), hi);
        st8b(gAg + ipos(kg + 2560, b), lo);
        st8h(aqx + qpos16(256 + n, b), cvt4h(h));
    }
    if (t_next < Tt) {
        const float* src = g_emb + (((size_t)t_next * Bb) << 9);
        for (int i4 = blockIdx.x * 256 + threadIdx.x; i4 < Bb * Ee / 4; i4 += REC_CTAS * 256) {
            int m = i4 >> 7;
            int e = (i4 & 127) << 2;
            float4 v = *(const float4*)(src + ((size_t)m << 9) + e);
            unsigned long long hi, lo;
            cvt4(v, hi, lo);
            st8b(gApq + ipos(e, m), hi);
            st8b(gApq + ipos(e + 1024, m), hi);
            st8b(gApq + ipos(e + 2048, m), lo);
            st8b(gAg + ipos(e, m), hi);
            st8b(gAg + ipos(e + 1280, m), hi);
            st8b(gAg + ipos(e + 2560, m), lo);
        }
    }
}

// ---------------- prologue: gates GEMM + LSTM tail (t=0 images) ----------------
__global__ void __launch_bounds__(256) prolog_kernel() {
    int seg = blockIdx.x >> 4, tile = blockIdx.x & 15;
    gemm_body(gAg + (size_t)seg * 15 * 8192,
              gBg + ((size_t)tile * NCH_G + seg * 15) * 8192,
              15, g_gp[seg], 2048, tile << 7);
    grid_barrier<REC_CTAS>(&g_ctrP);
    lstm_tail_body(0);
}

// ---------------- fused per-step recurrence kernel (64 CTAs) ----------------
__global__ void __launch_bounds__(256) rec_step_kernel(const float* __restrict__ noise,
                                                       float* __restrict__ out, int t) {
    {
        int seg = blockIdx.x >> 3, tile = blockIdx.x & 7;
        gemm_body(gApq + (size_t)seg * 6 * 8192,
                  gBpq + ((size_t)tile * NCH_PQ + seg * 6) * 8192,
                  6, g_pqp[seg], 1024, tile << 7);
    }
    grid_barrier<REC_CTAS>(&g_bar2[t][0]);
    z_tail_body(noise, out, t);
    signal_wait<REC_CTAS>(&g_flagZ[t]);   // barrier + producer signal for qx_persist
    {
        int seg = blockIdx.x >> 4, tile = blockIdx.x & 15;
        gemm_body(gAg + (size_t)seg * 15 * 8192,
                  gBg + ((size_t)tile * NCH_G + seg * 15) * 8192,
                  15, g_gp[seg], 2048, tile << 7);
    }
    grid_barrier<REC_CTAS>(&g_bar2[t][1]);
    // lstm_tail(t+1) writes qx A-buffer (t+1)%3, last read by qx(t-2)
    if (t >= 2) wait_count(&g_flagQ[t - 2], QX_CTAS);
    lstm_tail_body(t + 1);
}

// ---------------- persistent qx GEMM + log-softmax (84 CTAs, fp16, 3-stage) ----------------
#define STAGE_A16 (128 * PITCH)             // 18432
#define QSTG ((128 + 192) * PITCH)          // 46080
#define SMQX (3 * QSTG)                     // 138240

__device__ __forceinline__ void load_stage_qx(uint32_t st, const char* srcA, const char* srcB,
                                              int tid) {
#pragma unroll
    for (int j = 0; j < 4; j++) {          // A: 16KB
        int i = tid + j * 256;
        cpasync16(st + (i >> 3) * PITCH + (i & 7) * 16, srcA + i * 16);
    }
#pragma unroll
    for (int j = 0; j < 6; j++) {          // B: 24KB
        int i = tid + j * 256;
        cpasync16(st + STAGE_A16 + (i >> 3) * PITCH + (i & 7) * 16, srcB + i * 16);
    }
    asm volatile("cp.async.commit_group;" ::: "memory");
}

// log-softmax over one row (256 threads)
__device__ void softmax_row(float* __restrict__ x) {
    __shared__ float sred[8];
    __shared__ float sval;
    const int tid = threadIdx.x;
    float m = -3.4e38f;
    for (int i = tid; i < Vv; i += 256) m = fmaxf(m, x[i]);
#pragma unroll
    for (int o = 16; o; o >>= 1) m = fmaxf(m, __shfl_xor_sync(0xffffffffu, m, o));
    if ((tid & 31) == 0) sred[tid >> 5] = m;
    __syncthreads();
    if (tid < 32) {
        float v = (tid < 8) ? sred[tid] : -3.4e38f;
#pragma unroll
        for (int o = 4; o; o >>= 1) v = fmaxf(v, __shfl_xor_sync(0xffffffffu, v, o));
        if (tid == 0) sval = v;
    }
    __syncthreads();
    m = sval;
    float s = 0.0f;
    for (int i = tid; i < Vv; i += 256) s += expf(x[i] - m);
#pragma unroll
    for (int o = 16; o; o >>= 1) s += __shfl_xor_sync(0xffffffffu, s, o);
    __syncthreads();
    if ((tid & 31) == 0) sred[tid >> 5] = s;
    __syncthreads();
    if (tid < 32) {
        float v = (tid < 8) ? sred[tid] : 0.0f;
#pragma unroll
        for (int o = 4; o; o >>= 1) v += __shfl_xor_sync(0xffffffffu, v, o);
        if (tid == 0) sval = m + logf(v);
    }
    __syncthreads();
    float lz = sval;
    for (int i = tid; i < Vv; i += 256) x[i] -= lz;
    __syncthreads();
}

__global__ void __launch_bounds__(256) qx_persist_kernel(const float* __restrict__ qx_b,
                                                         float* __restrict__ out) {
    extern __shared__ __align__(16) char smem[];
    const uint32_t sb = s2u(smem);
    const int tid = threadIdx.x;
    const int wid = tid >> 5;
    const int lane = tid & 31;
    const int warp_m = wid >> 2;
    const int warp_n = wid & 3;
    const int n0 = blockIdx.x * QROWS;

    const char* gB = (const char*)(gBqx + (size_t)blockIdx.x * (QCH * QROWS * 64));

    const int a_row = lane & 15;
    const int a_coff = (lane >> 4) << 4;
    const int b_row = ((lane >> 4) << 3) | (lane & 7);
    const int b_coff = ((lane >> 3) & 1) << 4;
    const int g = lane >> 2, tq = lane & 3;

    for (int t = 0; t < Tt; t++) {
        wait_count(&g_flagZ[t], REC_CTAS);

        float* dst = out + OFF_QX + (size_t)t * Bb * Vv;
        const char* gA = (const char*)gAqx3[t % 3];

        float acc[4][6][4];
#pragma unroll
        for (int i = 0; i < 4; i++)
#pragma unroll
            for (int j = 0; j < 6; j++)
#pragma unroll
                for (int q = 0; q < 4; q++) acc[i][j][q] = 0.0f;

#pragma unroll
        for (int s = 0; s < 3; s++)
            load_stage_qx(sb + s * QSTG, gA + (size_t)s * 16384, gB + (size_t)s * 24576, tid);

        int slot = 0;
        for (int c = 0; c < QCH; c++) {
            asm volatile("cp.async.wait_group 2;" ::: "memory");
            __syncthreads();

            const uint32_t As = sb + slot * QSTG;
            const uint32_t Bs = As + STAGE_A16;
#pragma unroll
            for (int ks = 0; ks < 4; ks++) {
                uint32_t a[4][4];
#pragma unroll
                for (int mi = 0; mi < 4; mi++)
                    ldmatrix_x4(a[mi], As + (uint32_t)(warp_m * 64 + mi * 16 + a_row) * PITCH +
                                        ks * 32 + a_coff);
#pragma unroll
                for (int jp = 0; jp < 3; jp++) {
                    uint32_t b[4];
                    ldmatrix_x4(b, Bs + (uint32_t)(warp_n * 48 + jp * 16 + b_row) * PITCH +
                                    ks * 32 + b_coff);
#pragma unroll
                    for (int mi = 0; mi < 4; mi++) {
                        mma_f16(acc[mi][jp * 2 + 0], a[mi], b[0], b[1]);
                        mma_f16(acc[mi][jp * 2 + 1], a[mi], b[2], b[3]);
                    }
                }
            }
            __syncthreads();
            if (c + 3 < QCH)
                load_stage_qx(sb + slot * QSTG, gA + (size_t)(c + 3) * 16384,
                              gB + (size_t)(c + 3) * 24576, tid);
            else
                asm volatile("cp.async.commit_group;" ::: "memory");
            slot = (slot == 2) ? 0 : slot + 1;
        }

#pragma unroll
        for (int mi = 0; mi < 4; mi++) {
            int row = warp_m * 64 + mi * 16 + g;
#pragma unroll
            for (int nj = 0; nj < 6; nj++) {
                int col = n0 + warp_n * 48 + nj * 8 + 2 * tq;
                if (col >= Vv) continue;
                float b0 = qx_b[col], b1 = qx_b[col + 1];
                *(float2*)(dst + (size_t)row * Vv + col) =
                    make_float2(acc[mi][nj][0] + b0, acc[mi][nj][1] + b1);
                *(float2*)(dst + (size_t)(row + 8) * Vv + col) =
                    make_float2(acc[mi][nj][2] + b0, acc[mi][nj][3] + b1);
            }
        }

        // GEMM done: signal rec (A-buffer free) + all-84 barrier for softmax
        signal_wait<QX_CTAS>(&g_flagQ[t]);
        softmax_row(dst + (size_t)blockIdx.x * Vv);
        if (blockIdx.x + QX_CTAS < Bb)
            softmax_row(dst + (size_t)(blockIdx.x + QX_CTAS) * Vv);
    }
}

extern "C" void kernel_launch(void* const* d_in, const int* in_sizes, int n_in,
                              void* d_out, int out_size) {
    const float* features = (const float*)d_in[0];
    const int* captions = (const int*)d_in[1];
    const float* noise   = (const float*)d_in[3];
    const float* embed_W = (const float*)d_in[4];
    const float* W_ih    = (const float*)d_in[5];
    const float* W_hh    = (const float*)d_in[6];
    const float* b_ih    = (const float*)d_in[7];
    const float* b_hh    = (const float*)d_in[8];
    const float* qz_W    = (const float*)d_in[9];
    const float* qz_b    = (const float*)d_in[10];
    const float* prior_W = (const float*)d_in[11];
    const float* prior_b = (const float*)d_in[12];
    const float* qx_W    = (const float*)d_in[13];
    const float* qx_b    = (const float*)d_in[14];
    float* out = (float*)d_out;

    static cudaStream_t s1 = nullptr, s2 = nullptr;
    static cudaEvent_t evF = nullptr, evW = nullptr, evJ1 = nullptr;
    if (s1 == nullptr) {
        cudaStreamCreateWithFlags(&s1, cudaStreamNonBlocking);
        cudaStreamCreateWithFlags(&s2, cudaStreamNonBlocking);
        cudaEventCreateWithFlags(&evF, cudaEventDisableTiming);
        cudaEventCreateWithFlags(&evW, cudaEventDisableTiming);
        cudaEventCreateWithFlags(&evJ1, cudaEventDisableTiming);
    }

    cudaFuncSetAttribute(prolog_kernel, cudaFuncAttributeMaxDynamicSharedMemorySize, SM128);
    cudaFuncSetAttribute(rec_step_kernel, cudaFuncAttributeMaxDynamicSharedMemorySize, SM128);
    cudaFuncSetAttribute(qx_persist_kernel, cudaFuncAttributeMaxDynamicSharedMemorySize, SMQX);

    // one-time prep — fork side streams from the capture stream via an event
    prep_misc_kernel<<<(PREP_MISC_TOT + 255) / 256, 256>>>(b_ih, b_hh, qz_b, prior_b,
                                                           embed_W, captions);
    cudaEventRecord(evF, 0);
    cudaStreamWaitEvent(s1, evF, 0);
    cudaStreamWaitEvent(s2, evF, 0);
    prep_wqx_kernel<<<(16128 * 192 + 255) / 256, 256, 0, s1>>>(qx_W);
    prep_wg_kernel<<<(2048 * 320 + 255) / 256, 256, 0, s2>>>(W_ih, W_hh);
    prep_wpq_kernel<<<(1024 * 256 + 255) / 256, 256>>>(qz_W, prior_W);
    cudaEventRecord(evW, s2);
    cudaStreamWaitEvent(0, evW, 0);   // gBg ready before prolog on stream 0

    // persistent qx worker (spins on flagZ; safe to launch now on s1)
    qx_persist_kernel<<<QX_CTAS, 256, SMQX, s1>>>(qx_b, out);

    // initial LSTM step: features through the gates tc path (z,h image sections are zero)
    build_feat_kernel<<<32, 512>>>(features);
    prolog_kernel<<<REC_CTAS, 256, SM128>>>();

    for (int t = 0; t < Tt; t++)
        rec_step_kernel<<<REC_CTAS, 256, SM128>>>(noise, out, t);

    // join: wait for the persistent qx kernel
    cudaEventRecord(evJ1, s1);
    cudaStreamWaitEvent(0, evJ1, 0);
}